// round 3
// baseline (speedup 1.0000x reference)
#include <cuda_runtime.h>
#include <cstdint>

#define D_MODEL 2048
#define D_STATE 16
#define D_INNER 4096
#define BATCH   2048
#define LN_EPS  1e-5f

// ---------------- scratch (device globals: allocation-free) ----------------
__device__ float g_xn[(size_t)BATCH * D_MODEL];          // 16 MB
__device__ float g_xz[(size_t)BATCH * 2 * D_INNER];      // 64 MB
__device__ float g_yg[(size_t)BATCH * D_INNER];          // 32 MB
__device__ float g_A [D_INNER * D_STATE];                // 256 KB

// ---------------- A = exp(log_A) ----------------
__global__ void expA_kernel(const float* __restrict__ log_A) {
    int i = blockIdx.x * 256 + threadIdx.x;
    if (i < D_INNER * D_STATE) g_A[i] = expf(log_A[i]);
}

// ---------------- LayerNorm: one block per row ----------------
__global__ __launch_bounds__(256) void ln_kernel(const float* __restrict__ x,
                                                 const float* __restrict__ gamma,
                                                 const float* __restrict__ beta) {
    int b = blockIdx.x, tid = threadIdx.x;
    const float4* xr = (const float4*)(x + (size_t)b * D_MODEL);
    float4 v0 = xr[tid];
    float4 v1 = xr[tid + 256];
    float s = v0.x + v0.y + v0.z + v0.w + v1.x + v1.y + v1.z + v1.w;
    float q = v0.x*v0.x + v0.y*v0.y + v0.z*v0.z + v0.w*v0.w
            + v1.x*v1.x + v1.y*v1.y + v1.z*v1.z + v1.w*v1.w;
    #pragma unroll
    for (int o = 16; o; o >>= 1) {
        s += __shfl_xor_sync(0xffffffffu, s, o);
        q += __shfl_xor_sync(0xffffffffu, q, o);
    }
    __shared__ float rs[8], rq[8];
    int w = tid >> 5, l = tid & 31;
    if (l == 0) { rs[w] = s; rq[w] = q; }
    __syncthreads();
    s = rs[0] + rs[1] + rs[2] + rs[3] + rs[4] + rs[5] + rs[6] + rs[7];
    q = rq[0] + rq[1] + rq[2] + rq[3] + rq[4] + rq[5] + rq[6] + rq[7];
    float mean = s * (1.0f / D_MODEL);
    float var  = q * (1.0f / D_MODEL) - mean * mean;
    float rstd = rsqrtf(var + LN_EPS);
    const float4* gr = (const float4*)gamma;
    const float4* br = (const float4*)beta;
    float4 g0 = gr[tid], g1 = gr[tid + 256];
    float4 b0 = br[tid], b1 = br[tid + 256];
    float4 o0, o1;
    o0.x = (v0.x - mean) * rstd * g0.x + b0.x;
    o0.y = (v0.y - mean) * rstd * g0.y + b0.y;
    o0.z = (v0.z - mean) * rstd * g0.z + b0.z;
    o0.w = (v0.w - mean) * rstd * g0.w + b0.w;
    o1.x = (v1.x - mean) * rstd * g1.x + b1.x;
    o1.y = (v1.y - mean) * rstd * g1.y + b1.y;
    o1.z = (v1.z - mean) * rstd * g1.z + b1.z;
    o1.w = (v1.w - mean) * rstd * g1.w + b1.w;
    float4* out = (float4*)(g_xn + (size_t)b * D_MODEL);
    out[tid] = o0;
    out[tid + 256] = o1;
}

// ---------------- fp32 NT GEMM: C[M,N] = A[M,K] * B[N,K]^T (+ residual) ----
// 128x128 block tile, BK=16, 8x8 per thread, 256 threads.
__global__ __launch_bounds__(256) void gemm_nt_kernel(
    const float* __restrict__ A, const float* __restrict__ B,
    float* __restrict__ C, const float* __restrict__ R,
    int M, int N, int K)
{
    __shared__ float As[16][128];
    __shared__ float Bs[16][128];
    const int tid  = threadIdx.x;
    const int bm   = blockIdx.y * 128;
    const int bn   = blockIdx.x * 128;
    const int ty   = tid >> 4;         // 0..15
    const int tx   = tid & 15;         // 0..15
    const int row0 = ty * 8;
    const int col0 = tx * 8;
    const int lr   = tid >> 2;         // 0..63
    const int lk   = (tid & 3) << 2;   // 0,4,8,12

    float acc[8][8];
    #pragma unroll
    for (int i = 0; i < 8; i++)
        #pragma unroll
        for (int j = 0; j < 8; j++) acc[i][j] = 0.0f;

    const float* Ab = A + (size_t)bm * K;
    const float* Bb = B + (size_t)bn * K;

    for (int k0 = 0; k0 < K; k0 += 16) {
        #pragma unroll
        for (int t = 0; t < 2; t++) {
            int r = lr + t * 64;
            float4 va = *(const float4*)(Ab + (size_t)r * K + k0 + lk);
            As[lk + 0][r] = va.x; As[lk + 1][r] = va.y;
            As[lk + 2][r] = va.z; As[lk + 3][r] = va.w;
            float4 vb = *(const float4*)(Bb + (size_t)r * K + k0 + lk);
            Bs[lk + 0][r] = vb.x; Bs[lk + 1][r] = vb.y;
            Bs[lk + 2][r] = vb.z; Bs[lk + 3][r] = vb.w;
        }
        __syncthreads();
        #pragma unroll
        for (int k = 0; k < 16; k++) {
            float ra[8], rb[8];
            *(float4*)&ra[0] = *(const float4*)&As[k][row0];
            *(float4*)&ra[4] = *(const float4*)&As[k][row0 + 4];
            *(float4*)&rb[0] = *(const float4*)&Bs[k][col0];
            *(float4*)&rb[4] = *(const float4*)&Bs[k][col0 + 4];
            #pragma unroll
            for (int i = 0; i < 8; i++)
                #pragma unroll
                for (int j = 0; j < 8; j++)
                    acc[i][j] = fmaf(ra[i], rb[j], acc[i][j]);
        }
        __syncthreads();
    }

    #pragma unroll
    for (int i = 0; i < 8; i++) {
        size_t off = (size_t)(bm + row0 + i) * N + bn + col0;
        float4 o0 = make_float4(acc[i][0], acc[i][1], acc[i][2], acc[i][3]);
        float4 o1 = make_float4(acc[i][4], acc[i][5], acc[i][6], acc[i][7]);
        if (R) {
            float4 r0 = *(const float4*)(R + off);
            float4 r1 = *(const float4*)(R + off + 4);
            o0.x += r0.x; o0.y += r0.y; o0.z += r0.z; o0.w += r0.w;
            o1.x += r1.x; o1.y += r1.y; o1.z += r1.z; o1.w += r1.w;
        }
        *(float4*)(C + off)     = o0;
        *(float4*)(C + off + 4) = o1;
    }
}

// ---------------- fused SSM: one block per batch row ----------------
// Reads g_xz (x_main | z), W_xp, h; writes h_new (into d_out) and g_yg.
__global__ __launch_bounds__(256) void ssm_kernel(
    const float* __restrict__ h, const float* __restrict__ W_xp,
    const float* __restrict__ dt_bias, const float* __restrict__ Dp,
    float* __restrict__ h_new)
{
    int b = blockIdx.x, tid = threadIdx.x;
    __shared__ float s_xm[D_INNER];
    __shared__ float s_bc[33];

    // stage x_main row into smem
    const float4* xr = (const float4*)(g_xz + (size_t)b * 2 * D_INNER);
    float4* s4 = (float4*)s_xm;
    #pragma unroll
    for (int i = 0; i < 4; i++) s4[tid + i * 256] = xr[tid + i * 256];
    __syncthreads();

    // xp = x_main @ W_xp^T : 33 outputs (B[0:16], C[16:32], delta_raw[32])
    int w = tid >> 5, l = tid & 31;
    for (int j = w; j < 33; j += 8) {
        const float* wr = W_xp + (size_t)j * D_INNER;
        float a = 0.0f;
        for (int k = l; k < D_INNER; k += 32) a += s_xm[k] * wr[k];
        #pragma unroll
        for (int o = 16; o; o >>= 1) a += __shfl_xor_sync(0xffffffffu, a, o);
        if (l == 0) s_bc[j] = a;
    }
    __syncthreads();

    float draw = s_bc[32];
    float Bv[16], Cv[16];
    #pragma unroll
    for (int s = 0; s < 16; s++) { Bv[s] = s_bc[s]; Cv[s] = s_bc[16 + s]; }

    const float* zrow = g_xz + (size_t)b * 2 * D_INNER + D_INNER;

    for (int d = tid; d < D_INNER; d += 256) {
        float xm = s_xm[d];
        float t  = draw + dt_bias[d];
        float dlt = (t > 20.0f) ? t : log1pf(expf(t));   // softplus
        size_t off = ((size_t)b * D_INNER + d) * D_STATE;
        const float4* hr = (const float4*)(h + off);
        float4*       ho = (float4*)(h_new + off);
        const float4* Ar = (const float4*)(g_A + d * D_STATE);
        float accv = 0.0f;
        #pragma unroll
        for (int q = 0; q < 4; q++) {
            float4 hv = hr[q];
            float4 av = Ar[q];
            float4 o;
            o.x = expf(-dlt * av.x) * hv.x + dlt * Bv[4*q + 0] * xm;
            o.y = expf(-dlt * av.y) * hv.y + dlt * Bv[4*q + 1] * xm;
            o.z = expf(-dlt * av.z) * hv.z + dlt * Bv[4*q + 2] * xm;
            o.w = expf(-dlt * av.w) * hv.w + dlt * Bv[4*q + 3] * xm;
            ho[q] = o;
            accv += o.x * Cv[4*q + 0] + o.y * Cv[4*q + 1]
                  + o.z * Cv[4*q + 2] + o.w * Cv[4*q + 3];
        }
        float y = accv + Dp[d] * xm;
        float z = zrow[d];
        float sig = 1.0f / (1.0f + expf(-z));
        g_yg[(size_t)b * D_INNER + d] = y * z * sig;   // y_ssm * silu(z)
    }
}

// ---------------- launch ----------------
extern "C" void kernel_launch(void* const* d_in, const int* in_sizes, int n_in,
                              void* d_out, int out_size) {
    const float* x     = (const float*)d_in[0];
    const float* h     = (const float*)d_in[1];
    const float* W_in  = (const float*)d_in[2];
    const float* W_xp  = (const float*)d_in[3];
    const float* log_A = (const float*)d_in[4];
    const float* dt_b  = (const float*)d_in[5];
    const float* Dp    = (const float*)d_in[6];
    const float* W_out = (const float*)d_in[7];
    const float* gamma = (const float*)d_in[8];
    const float* beta  = (const float*)d_in[9];

    float* y_out = (float*)d_out;                                // [2048, 2048]
    float* h_out = y_out + (size_t)BATCH * D_MODEL;              // [2048, 4096, 16]

    void* p;
    cudaGetSymbolAddress(&p, g_xn); float* xn = (float*)p;
    cudaGetSymbolAddress(&p, g_xz); float* xz = (float*)p;
    cudaGetSymbolAddress(&p, g_yg); float* yg = (float*)p;

    expA_kernel<<<(D_INNER * D_STATE + 255) / 256, 256>>>(log_A);
    ln_kernel<<<BATCH, 256>>>(x, gamma, beta);
    // xz[B, 8192] = xn[B,2048] @ W_in[8192,2048]^T
    gemm_nt_kernel<<<dim3(2 * D_INNER / 128, BATCH / 128), 256>>>(
        xn, W_in, xz, nullptr, BATCH, 2 * D_INNER, D_MODEL);
    // SSM: reads xz, writes h_new (d_out) + g_yg
    ssm_kernel<<<BATCH, 256>>>(h, W_xp, dt_b, Dp, h_out);
    // y[B,2048] = yg[B,4096] @ W_out[2048,4096]^T + x  (residual fused)
    gemm_nt_kernel<<<dim3(D_MODEL / 128, BATCH / 128), 256>>>(
        yg, W_out, y_out, x, BATCH, D_MODEL, D_INNER);
}

// round 7
// speedup vs baseline: 2.1973x; 2.1973x over previous
#include <cuda_runtime.h>
#include <cuda_bf16.h>
#include <cstdint>

#define D_MODEL 2048
#define D_STATE 16
#define D_INNER 4096
#define BATCH   2048
#define LN_EPS  1e-5f

// ---------------- scratch (device globals: allocation-free) ----------------
__device__ float g_xz [(size_t)BATCH * 2 * D_INNER];          // 64 MB (x_main | z)
__device__ float g_A  [D_INNER * D_STATE];
__device__ float g_bcd[(size_t)BATCH * 33];                   // B(16) C(16) delta_raw(1)
__device__ __nv_bfloat16 g_xh [(size_t)BATCH * D_MODEL];
__device__ __nv_bfloat16 g_xl [(size_t)BATCH * D_MODEL];
__device__ __nv_bfloat16 g_wih[(size_t)2 * D_INNER * D_MODEL];
__device__ __nv_bfloat16 g_wil[(size_t)2 * D_INNER * D_MODEL];
__device__ __nv_bfloat16 g_woh[(size_t)D_MODEL * D_INNER];
__device__ __nv_bfloat16 g_wol[(size_t)D_MODEL * D_INNER];
__device__ __nv_bfloat16 g_ygh[(size_t)BATCH * D_INNER];
__device__ __nv_bfloat16 g_ygl[(size_t)BATCH * D_INNER];

// ---------------- helpers ----------------
__device__ __forceinline__ uint32_t smem_u32(const void* p) {
    uint32_t a;
    asm("{ .reg .u64 t; cvta.to.shared.u64 t, %1; cvt.u32.u64 %0, t; }" : "=r"(a) : "l"(p));
    return a;
}
__device__ __forceinline__ void ldsm4(uint32_t (&r)[4], uint32_t addr) {
    asm volatile("ldmatrix.sync.aligned.m8n8.x4.shared.b16 {%0,%1,%2,%3}, [%4];"
        : "=r"(r[0]), "=r"(r[1]), "=r"(r[2]), "=r"(r[3]) : "r"(addr));
}
__device__ __forceinline__ void mma16816(float (&c)[4], const uint32_t (&a)[4],
                                         uint32_t b0, uint32_t b1) {
    asm volatile("mma.sync.aligned.m16n8k16.row.col.f32.bf16.bf16.f32 "
        "{%0,%1,%2,%3}, {%4,%5,%6,%7}, {%8,%9}, {%0,%1,%2,%3};"
        : "+f"(c[0]), "+f"(c[1]), "+f"(c[2]), "+f"(c[3])
        : "r"(a[0]), "r"(a[1]), "r"(a[2]), "r"(a[3]), "r"(b0), "r"(b1));
}

// ---------------- small kernels ----------------
__global__ void expA_kernel(const float* __restrict__ log_A) {
    int i = blockIdx.x * 256 + threadIdx.x;
    if (i < D_INNER * D_STATE) g_A[i] = expf(log_A[i]);
}

__device__ __forceinline__ void st_split4(float4 o, __nv_bfloat16* hp, __nv_bfloat16* lp) {
    __nv_bfloat16 h0 = __float2bfloat16(o.x), h1 = __float2bfloat16(o.y);
    __nv_bfloat16 h2 = __float2bfloat16(o.z), h3 = __float2bfloat16(o.w);
    __nv_bfloat162 a, b;
    a.x = h0; a.y = h1; b.x = h2; b.y = h3;
    *(__nv_bfloat162*)(hp)     = a;
    *(__nv_bfloat162*)(hp + 2) = b;
    __nv_bfloat162 c, d;
    c.x = __float2bfloat16(o.x - __bfloat162float(h0));
    c.y = __float2bfloat16(o.y - __bfloat162float(h1));
    d.x = __float2bfloat16(o.z - __bfloat162float(h2));
    d.y = __float2bfloat16(o.w - __bfloat162float(h3));
    *(__nv_bfloat162*)(lp)     = c;
    *(__nv_bfloat162*)(lp + 2) = d;
}

__global__ __launch_bounds__(256) void split_kernel(const float* __restrict__ s,
                                                    __nv_bfloat16* __restrict__ hi,
                                                    __nv_bfloat16* __restrict__ lo, int n4) {
    int i = blockIdx.x * 256 + threadIdx.x;
    if (i >= n4) return;
    float4 v = ((const float4*)s)[i];
    st_split4(v, hi + (size_t)i * 4, lo + (size_t)i * 4);
}

// LayerNorm -> split bf16 hi/lo directly
__global__ __launch_bounds__(256) void ln_kernel(const float* __restrict__ x,
                                                 const float* __restrict__ gamma,
                                                 const float* __restrict__ beta) {
    int b = blockIdx.x, tid = threadIdx.x;
    const float4* xr = (const float4*)(x + (size_t)b * D_MODEL);
    float4 v0 = xr[tid];
    float4 v1 = xr[tid + 256];
    float s = v0.x + v0.y + v0.z + v0.w + v1.x + v1.y + v1.z + v1.w;
    float q = v0.x*v0.x + v0.y*v0.y + v0.z*v0.z + v0.w*v0.w
            + v1.x*v1.x + v1.y*v1.y + v1.z*v1.z + v1.w*v1.w;
    #pragma unroll
    for (int o = 16; o; o >>= 1) {
        s += __shfl_xor_sync(0xffffffffu, s, o);
        q += __shfl_xor_sync(0xffffffffu, q, o);
    }
    __shared__ float rs[8], rq[8];
    int w = tid >> 5, l = tid & 31;
    if (l == 0) { rs[w] = s; rq[w] = q; }
    __syncthreads();
    s = rs[0]+rs[1]+rs[2]+rs[3]+rs[4]+rs[5]+rs[6]+rs[7];
    q = rq[0]+rq[1]+rq[2]+rq[3]+rq[4]+rq[5]+rq[6]+rq[7];
    float mean = s * (1.0f / D_MODEL);
    float var  = q * (1.0f / D_MODEL) - mean * mean;
    float rstd = rsqrtf(var + LN_EPS);
    const float4* gr = (const float4*)gamma;
    const float4* br = (const float4*)beta;
    float4 g0 = gr[tid], g1 = gr[tid + 256];
    float4 b0 = br[tid], b1 = br[tid + 256];
    float4 o0, o1;
    o0.x = (v0.x-mean)*rstd*g0.x + b0.x;  o0.y = (v0.y-mean)*rstd*g0.y + b0.y;
    o0.z = (v0.z-mean)*rstd*g0.z + b0.z;  o0.w = (v0.w-mean)*rstd*g0.w + b0.w;
    o1.x = (v1.x-mean)*rstd*g1.x + b1.x;  o1.y = (v1.y-mean)*rstd*g1.y + b1.y;
    o1.z = (v1.z-mean)*rstd*g1.z + b1.z;  o1.w = (v1.w-mean)*rstd*g1.w + b1.w;
    size_t base = (size_t)b * D_MODEL;
    st_split4(o0, g_xh + base + tid*4,        g_xl + base + tid*4);
    st_split4(o1, g_xh + base + 1024 + tid*4, g_xl + base + 1024 + tid*4);
}

// ---------------- mma.sync split-bf16 NT GEMM ----------------
// C[M,N] = A[M,K]*B[N,K]^T (+R).  A/B as hi/lo bf16 pairs, 3-term accumulate.
// CTA: 128x128, BK=32, 8 warps (2x4), warp tile 64x32. 3-stage cp.async.
#define GBK        32
#define ROW_B      80                                  // padded row bytes (40 elems)
#define MAT_BYTES  (128 * ROW_B)                       // 10240
#define STG_BYTES  (4 * MAT_BYTES)                     // 40960 (Ah|Al|Bh|Bl)
#define NSTAGE     3
#define GEMM_SMEM  (NSTAGE * STG_BYTES)                // 122880

__device__ __forceinline__ void ld_mat32(uint32_t dst, const __nv_bfloat16* __restrict__ G,
                                         int rb, int k0, int K, int tid) {
    #pragma unroll
    for (int i = 0; i < 2; i++) {
        int c = tid + i * 256;                 // 0..511
        int row = c >> 2, kc = c & 3;
        uint32_t d = dst + (uint32_t)(row * ROW_B + kc * 16);
        const __nv_bfloat16* s = G + (size_t)(rb + row) * K + k0 + kc * 8;
        asm volatile("cp.async.cg.shared.global [%0], [%1], 16;\n" :: "r"(d), "l"(s) : "memory");
    }
}

__global__ __launch_bounds__(256) void gemm_mma_kernel(
    const __nv_bfloat16* __restrict__ Ah, const __nv_bfloat16* __restrict__ Al,
    const __nv_bfloat16* __restrict__ Bh, const __nv_bfloat16* __restrict__ Bl,
    float* __restrict__ C, const float* __restrict__ Rp, int M, int N, int K)
{
    extern __shared__ char smem_raw[];
    uint32_t sbase = smem_u32(smem_raw);
    const int tid = threadIdx.x, wid = tid >> 5, lane = tid & 31;
    const int bm = blockIdx.y * 128, bn = blockIdx.x * 128;
    const int warp_m = (wid >> 2) * 64;        // 0 or 64
    const int warp_n = (wid & 3) * 32;         // 0,32,64,96
    const int NCH = K / GBK;

    float acc[4][4][4];
    #pragma unroll
    for (int i = 0; i < 4; i++)
        #pragma unroll
        for (int n = 0; n < 4; n++)
            #pragma unroll
            for (int e = 0; e < 4; e++) acc[i][n][e] = 0.0f;

    // lane-dependent ldmatrix address components
    const int arow = lane & 15;                         // A: rows m0..m0+15
    const int acol = (lane >> 4) << 3;                  // A: k-half select
    const int brow = ((lane >> 4) << 3) + (lane & 7);   // B: n within 16
    const int bcol = ((lane >> 3) & 1) << 3;            // B: k-half select

    // prologue: stages 0,1 = chunks 0,1
    #pragma unroll
    for (int p = 0; p < 2; p++) {
        uint32_t sb = sbase + p * STG_BYTES;
        ld_mat32(sb,                 Ah, bm, p * GBK, K, tid);
        ld_mat32(sb + MAT_BYTES,     Al, bm, p * GBK, K, tid);
        ld_mat32(sb + 2 * MAT_BYTES, Bh, bn, p * GBK, K, tid);
        ld_mat32(sb + 3 * MAT_BYTES, Bl, bn, p * GBK, K, tid);
        asm volatile("cp.async.commit_group;\n" ::: "memory");
    }

    for (int j = 0; j < NCH; j++) {
        asm volatile("cp.async.wait_group 1;\n" ::: "memory");
        __syncthreads();

        // prefetch chunk j+2 into stage (j+2)%3 (consumed at j-1; safe after sync)
        if (j + 2 < NCH) {
            uint32_t sb = sbase + ((j + 2) % NSTAGE) * STG_BYTES;
            int k0 = (j + 2) * GBK;
            ld_mat32(sb,                 Ah, bm, k0, K, tid);
            ld_mat32(sb + MAT_BYTES,     Al, bm, k0, K, tid);
            ld_mat32(sb + 2 * MAT_BYTES, Bh, bn, k0, K, tid);
            ld_mat32(sb + 3 * MAT_BYTES, Bl, bn, k0, K, tid);
        }
        asm volatile("cp.async.commit_group;\n" ::: "memory");

        uint32_t sb = sbase + (j % NSTAGE) * STG_BYTES;
        #pragma unroll
        for (int ks = 0; ks < 2; ks++) {
            const int k0 = ks * 16;
            uint32_t ahf[4][4], alf[4][4], bhf[2][4], blf[2][4];
            #pragma unroll
            for (int i = 0; i < 4; i++) {
                uint32_t off = (uint32_t)((warp_m + i * 16 + arow) * ROW_B + (k0 + acol) * 2);
                ldsm4(ahf[i], sb + off);
                ldsm4(alf[i], sb + MAT_BYTES + off);
            }
            #pragma unroll
            for (int jn = 0; jn < 2; jn++) {
                uint32_t off = (uint32_t)((warp_n + jn * 16 + brow) * ROW_B + (k0 + bcol) * 2);
                ldsm4(bhf[jn], sb + 2 * MAT_BYTES + off);
                ldsm4(blf[jn], sb + 3 * MAT_BYTES + off);
            }
            #pragma unroll
            for (int i = 0; i < 4; i++) {
                #pragma unroll
                for (int n = 0; n < 4; n++) {
                    uint32_t bh0 = bhf[n >> 1][(n & 1) * 2], bh1 = bhf[n >> 1][(n & 1) * 2 + 1];
                    uint32_t bl0 = blf[n >> 1][(n & 1) * 2], bl1 = blf[n >> 1][(n & 1) * 2 + 1];
                    mma16816(acc[i][n], ahf[i], bh0, bh1);
                    mma16816(acc[i][n], ahf[i], bl0, bl1);
                    mma16816(acc[i][n], alf[i], bh0, bh1);
                }
            }
        }
    }

    // epilogue: thread (lane) holds rows m0+lane/4, m0+lane/4+8; cols 2*(lane%4)
    #pragma unroll
    for (int i = 0; i < 4; i++) {
        int r0 = bm + warp_m + i * 16 + (lane >> 2);
        #pragma unroll
        for (int n = 0; n < 4; n++) {
            int col = bn + warp_n + n * 8 + (lane & 3) * 2;
            float2 u0 = make_float2(acc[i][n][0], acc[i][n][1]);
            float2 u1 = make_float2(acc[i][n][2], acc[i][n][3]);
            size_t o0 = (size_t)r0 * N + col;
            size_t o1 = (size_t)(r0 + 8) * N + col;
            if (Rp) {
                float2 q0 = *(const float2*)(Rp + o0);
                float2 q1 = *(const float2*)(Rp + o1);
                u0.x += q0.x; u0.y += q0.y; u1.x += q1.x; u1.y += q1.y;
            }
            *(float2*)(C + o0) = u0;
            *(float2*)(C + o1) = u1;
        }
    }
}

// ---------------- xp: [B,33] = x_main @ W_xp^T, 8 rows/block ----------------
__global__ __launch_bounds__(256) void xp_kernel(const float* __restrict__ W_xp) {
    __shared__ float sx[8][256];
    __shared__ float sw[33][256];
    int tid = threadIdx.x, w = tid >> 5, lid = tid & 31;
    int b0 = blockIdx.x * 8;
    float acc[40];
    #pragma unroll
    for (int i = 0; i < 40; i++) acc[i] = 0.0f;

    for (int kc = 0; kc < D_INNER; kc += 256) {
        #pragma unroll
        for (int i = 0; i < 2; i++) {
            int idx = i * 256 + tid;               // < 512
            int r = idx >> 6, c = (idx & 63) << 2;
            *(float4*)&sx[r][c] =
                *(const float4*)(g_xz + (size_t)(b0 + r) * (2 * D_INNER) + kc + c);
        }
        #pragma unroll
        for (int i = 0; i < 9; i++) {
            int idx = i * 256 + tid;
            if (idx < 33 * 64) {
                int r = idx >> 6, c = (idx & 63) << 2;
                *(float4*)&sw[r][c] = *(const float4*)(W_xp + (size_t)r * D_INNER + kc + c);
            }
        }
        __syncthreads();
        #pragma unroll
        for (int jj = 0; jj < 5; jj++) {
            int j = w + jj * 8;
            if (j < 33) {
                #pragma unroll
                for (int kk = 0; kk < 8; kk++) {
                    float wv = sw[j][kk * 32 + lid];
                    #pragma unroll
                    for (int r = 0; r < 8; r++)
                        acc[jj * 8 + r] = fmaf(sx[r][kk * 32 + lid], wv, acc[jj * 8 + r]);
                }
            }
        }
        __syncthreads();
    }
    #pragma unroll
    for (int jj = 0; jj < 5; jj++) {
        int j = w + jj * 8;
        #pragma unroll
        for (int r = 0; r < 8; r++) {
            float a = acc[jj * 8 + r];
            #pragma unroll
            for (int o = 16; o; o >>= 1) a += __shfl_xor_sync(0xffffffffu, a, o);
            if (lid == 0 && j < 33) g_bcd[(size_t)(b0 + r) * 33 + j] = a;
        }
    }
}

// ---------------- elementwise SSM: thread per (b,d), B/C/delta via smem ------
__global__ __launch_bounds__(256) void ssm2_kernel(const float* __restrict__ h,
                                                   const float* __restrict__ dt_bias,
                                                   const float* __restrict__ Dp,
                                                   float* __restrict__ h_new) {
    int i = blockIdx.x * 256 + threadIdx.x;        // < BATCH*D_INNER
    int b = i >> 12;                               // all threads in block share b
    int d = i & (D_INNER - 1);

    __shared__ float s_bc[33];
    if (threadIdx.x < 33) s_bc[threadIdx.x] = g_bcd[(size_t)b * 33 + threadIdx.x];
    __syncthreads();

    float xm = g_xz[(size_t)b * (2 * D_INNER) + d];
    float z  = g_xz[(size_t)b * (2 * D_INNER) + D_INNER + d];
    float t = s_bc[32] + dt_bias[d];
    float dlt = (t > 20.0f) ? t : log1pf(__expf(t));
    size_t off = (size_t)i * D_STATE;
    const float4* hr = (const float4*)(h + off);
    float4*       ho = (float4*)(h_new + off);
    const float4* Ar = (const float4*)(g_A + d * D_STATE);
    float acc = 0.0f;
    #pragma unroll
    for (int q = 0; q < 4; q++) {
        float4 hv = hr[q], av = Ar[q];
        float4 o;
        o.x = __expf(-dlt * av.x) * hv.x + dlt * s_bc[4*q + 0] * xm;
        o.y = __expf(-dlt * av.y) * hv.y + dlt * s_bc[4*q + 1] * xm;
        o.z = __expf(-dlt * av.z) * hv.z + dlt * s_bc[4*q + 2] * xm;
        o.w = __expf(-dlt * av.w) * hv.w + dlt * s_bc[4*q + 3] * xm;
        ho[q] = o;
        acc += o.x * s_bc[16 + 4*q + 0] + o.y * s_bc[16 + 4*q + 1]
             + o.z * s_bc[16 + 4*q + 2] + o.w * s_bc[16 + 4*q + 3];
    }
    float y = acc + Dp[d] * xm;
    float sig = 1.0f / (1.0f + __expf(-z));
    float yg = y * z * sig;
    __nv_bfloat16 hi = __float2bfloat16(yg);
    g_ygh[i] = hi;
    g_ygl[i] = __float2bfloat16(yg - __bfloat162float(hi));
}

// ---------------- launch ----------------
extern "C" void kernel_launch(void* const* d_in, const int* in_sizes, int n_in,
                              void* d_out, int out_size) {
    const float* x     = (const float*)d_in[0];
    const float* h     = (const float*)d_in[1];
    const float* W_in  = (const float*)d_in[2];
    const float* W_xp  = (const float*)d_in[3];
    const float* log_A = (const float*)d_in[4];
    const float* dt_b  = (const float*)d_in[5];
    const float* Dp    = (const float*)d_in[6];
    const float* W_out = (const float*)d_in[7];
    const float* gamma = (const float*)d_in[8];
    const float* beta  = (const float*)d_in[9];

    float* y_out = (float*)d_out;                         // [2048, 2048]
    float* h_out = y_out + (size_t)BATCH * D_MODEL;       // [2048, 4096, 16]

    void* p;
    cudaGetSymbolAddress(&p, g_xz);  float* xz = (float*)p;
    cudaGetSymbolAddress(&p, g_xh);  __nv_bfloat16* xh  = (__nv_bfloat16*)p;
    cudaGetSymbolAddress(&p, g_xl);  __nv_bfloat16* xl  = (__nv_bfloat16*)p;
    cudaGetSymbolAddress(&p, g_wih); __nv_bfloat16* wih = (__nv_bfloat16*)p;
    cudaGetSymbolAddress(&p, g_wil); __nv_bfloat16* wil = (__nv_bfloat16*)p;
    cudaGetSymbolAddress(&p, g_woh); __nv_bfloat16* woh = (__nv_bfloat16*)p;
    cudaGetSymbolAddress(&p, g_wol); __nv_bfloat16* wol = (__nv_bfloat16*)p;
    cudaGetSymbolAddress(&p, g_ygh); __nv_bfloat16* ygh = (__nv_bfloat16*)p;
    cudaGetSymbolAddress(&p, g_ygl); __nv_bfloat16* ygl = (__nv_bfloat16*)p;

    cudaFuncSetAttribute(gemm_mma_kernel, cudaFuncAttributeMaxDynamicSharedMemorySize, GEMM_SMEM);

    expA_kernel<<<(D_INNER * D_STATE + 255) / 256, 256>>>(log_A);

    int n4_wi = (2 * D_INNER * D_MODEL) / 4;
    split_kernel<<<(n4_wi + 255) / 256, 256>>>(W_in, wih, wil, n4_wi);
    int n4_wo = (D_MODEL * D_INNER) / 4;
    split_kernel<<<(n4_wo + 255) / 256, 256>>>(W_out, woh, wol, n4_wo);

    ln_kernel<<<BATCH, 256>>>(x, gamma, beta);

    // GEMM1: xz[B, 8192] = xn @ W_in^T
    gemm_mma_kernel<<<dim3(2 * D_INNER / 128, BATCH / 128), 256, GEMM_SMEM>>>(
        xh, xl, wih, wil, xz, nullptr, BATCH, 2 * D_INNER, D_MODEL);

    xp_kernel<<<BATCH / 8, 256>>>(W_xp);

    ssm2_kernel<<<(BATCH * D_INNER) / 256, 256>>>(h, dt_b, Dp, h_out);

    // GEMM2: y[B, 2048] = y_gated @ W_out^T + x
    gemm_mma_kernel<<<dim3(D_MODEL / 128, BATCH / 128), 256, GEMM_SMEM>>>(
        ygh, ygl, woh, wol, y_out, x, BATCH, D_MODEL, D_INNER);
}

// round 9
// speedup vs baseline: 2.8073x; 1.2776x over previous
#include <cuda_runtime.h>
#include <cuda_fp16.h>
#include <cstdint>

#define D_MODEL 2048
#define D_STATE 16
#define D_INNER 4096
#define BATCH   2048
#define LN_EPS  1e-5f

// ---------------- scratch (device globals: allocation-free) ----------------
__device__ float g_xz [(size_t)BATCH * 2 * D_INNER];          // 64 MB (x_main | z)
__device__ float g_A  [D_INNER * D_STATE];
__device__ float g_bcd[(size_t)BATCH * 33];                   // B(16) C(16) delta_raw(1)
__device__ __half g_xh [(size_t)BATCH * D_MODEL];             // xn, fp16
__device__ __half g_wih[(size_t)2 * D_INNER * D_MODEL];       // W_in hi
__device__ __half g_wil[(size_t)2 * D_INNER * D_MODEL];       // W_in lo
__device__ __half g_woh[(size_t)D_MODEL * D_INNER];           // W_out hi
__device__ __half g_wol[(size_t)D_MODEL * D_INNER];           // W_out lo
__device__ __half g_yg [(size_t)BATCH * D_INNER];             // y_gated, fp16

// ---------------- helpers ----------------
__device__ __forceinline__ uint32_t smem_u32(const void* p) {
    uint32_t a;
    asm("{ .reg .u64 t; cvta.to.shared.u64 t, %1; cvt.u32.u64 %0, t; }" : "=r"(a) : "l"(p));
    return a;
}
__device__ __forceinline__ void ldsm4(uint32_t (&r)[4], uint32_t addr) {
    asm volatile("ldmatrix.sync.aligned.m8n8.x4.shared.b16 {%0,%1,%2,%3}, [%4];"
        : "=r"(r[0]), "=r"(r[1]), "=r"(r[2]), "=r"(r[3]) : "r"(addr));
}
__device__ __forceinline__ void mma16816(float (&c)[4], const uint32_t (&a)[4],
                                         uint32_t b0, uint32_t b1) {
    asm volatile("mma.sync.aligned.m16n8k16.row.col.f32.f16.f16.f32 "
        "{%0,%1,%2,%3}, {%4,%5,%6,%7}, {%8,%9}, {%0,%1,%2,%3};"
        : "+f"(c[0]), "+f"(c[1]), "+f"(c[2]), "+f"(c[3])
        : "r"(a[0]), "r"(a[1]), "r"(a[2]), "r"(a[3]), "r"(b0), "r"(b1));
}

// ---------------- small kernels ----------------
__global__ void expA_kernel(const float* __restrict__ log_A) {
    int i = blockIdx.x * 256 + threadIdx.x;
    if (i < D_INNER * D_STATE) g_A[i] = expf(log_A[i]);
}

// fp16 weight split: hi + lo, lo = round(w - hi)
__device__ __forceinline__ void st_wsplit4(float4 o, __half* hp, __half* lp) {
    __half h0 = __float2half(o.x), h1 = __float2half(o.y);
    __half h2 = __float2half(o.z), h3 = __float2half(o.w);
    __half2 a, b;
    a.x = h0; a.y = h1; b.x = h2; b.y = h3;
    *(__half2*)(hp)     = a;
    *(__half2*)(hp + 2) = b;
    __half2 c, d;
    c.x = __float2half(o.x - __half2float(h0));
    c.y = __float2half(o.y - __half2float(h1));
    d.x = __float2half(o.z - __half2float(h2));
    d.y = __float2half(o.w - __half2float(h3));
    *(__half2*)(lp)     = c;
    *(__half2*)(lp + 2) = d;
}

__global__ __launch_bounds__(256) void split_kernel(const float* __restrict__ s,
                                                    __half* __restrict__ hi,
                                                    __half* __restrict__ lo, int n4) {
    int i = blockIdx.x * 256 + threadIdx.x;
    if (i >= n4) return;
    float4 v = ((const float4*)s)[i];
    st_wsplit4(v, hi + (size_t)i * 4, lo + (size_t)i * 4);
}

// LayerNorm -> single fp16 xn
__global__ __launch_bounds__(256) void ln_kernel(const float* __restrict__ x,
                                                 const float* __restrict__ gamma,
                                                 const float* __restrict__ beta) {
    int b = blockIdx.x, tid = threadIdx.x;
    const float4* xr = (const float4*)(x + (size_t)b * D_MODEL);
    float4 v0 = xr[tid];
    float4 v1 = xr[tid + 256];
    float s = v0.x + v0.y + v0.z + v0.w + v1.x + v1.y + v1.z + v1.w;
    float q = v0.x*v0.x + v0.y*v0.y + v0.z*v0.z + v0.w*v0.w
            + v1.x*v1.x + v1.y*v1.y + v1.z*v1.z + v1.w*v1.w;
    #pragma unroll
    for (int o = 16; o; o >>= 1) {
        s += __shfl_xor_sync(0xffffffffu, s, o);
        q += __shfl_xor_sync(0xffffffffu, q, o);
    }
    __shared__ float rs[8], rq[8];
    int w = tid >> 5, l = tid & 31;
    if (l == 0) { rs[w] = s; rq[w] = q; }
    __syncthreads();
    s = rs[0]+rs[1]+rs[2]+rs[3]+rs[4]+rs[5]+rs[6]+rs[7];
    q = rq[0]+rq[1]+rq[2]+rq[3]+rq[4]+rq[5]+rq[6]+rq[7];
    float mean = s * (1.0f / D_MODEL);
    float var  = q * (1.0f / D_MODEL) - mean * mean;
    float rstd = rsqrtf(var + LN_EPS);
    const float4* gr = (const float4*)gamma;
    const float4* br = (const float4*)beta;
    float4 g0 = gr[tid], g1 = gr[tid + 256];
    float4 b0 = br[tid], b1 = br[tid + 256];
    size_t base = (size_t)b * D_MODEL;
    __half2 p0, p1, p2, p3;
    p0.x = __float2half((v0.x-mean)*rstd*g0.x + b0.x);
    p0.y = __float2half((v0.y-mean)*rstd*g0.y + b0.y);
    p1.x = __float2half((v0.z-mean)*rstd*g0.z + b0.z);
    p1.y = __float2half((v0.w-mean)*rstd*g0.w + b0.w);
    p2.x = __float2half((v1.x-mean)*rstd*g1.x + b1.x);
    p2.y = __float2half((v1.y-mean)*rstd*g1.y + b1.y);
    p3.x = __float2half((v1.z-mean)*rstd*g1.z + b1.z);
    p3.y = __float2half((v1.w-mean)*rstd*g1.w + b1.w);
    *(__half2*)(g_xh + base + tid*4)          = p0;
    *(__half2*)(g_xh + base + tid*4 + 2)      = p1;
    *(__half2*)(g_xh + base + 1024 + tid*4)   = p2;
    *(__half2*)(g_xh + base + 1024 + tid*4+2) = p3;
}

// ---------------- mma.sync 2-term fp16 NT GEMM ----------------
// C[M,N] = A[M,K]*(Bh+Bl)[N,K]^T (+R).  A single fp16, B split fp16 hi/lo.
// CTA: 128x128, BK=32, 8 warps (2x4), warp tile 64x32. 4-stage cp.async.
#define GBK        32
#define ROW_B      80                                  // padded row bytes (40 elems)
#define MAT_BYTES  (128 * ROW_B)                       // 10240
#define STG_BYTES  (3 * MAT_BYTES)                     // 30720 (A|Bh|Bl)
#define NSTAGE     4
#define GEMM_SMEM  (NSTAGE * STG_BYTES)                // 122880

__device__ __forceinline__ void ld_mat32(uint32_t dst, const __half* __restrict__ G,
                                         int rb, int k0, int K, int tid) {
    #pragma unroll
    for (int i = 0; i < 2; i++) {
        int c = tid + i * 256;                 // 0..511
        int row = c >> 2, kc = c & 3;
        uint32_t d = dst + (uint32_t)(row * ROW_B + kc * 16);
        const __half* s = G + (size_t)(rb + row) * K + k0 + kc * 8;
        asm volatile("cp.async.cg.shared.global [%0], [%1], 16;\n" :: "r"(d), "l"(s) : "memory");
    }
}

__global__ __launch_bounds__(256) void gemm_mma_kernel(
    const __half* __restrict__ A,
    const __half* __restrict__ Bh, const __half* __restrict__ Bl,
    float* __restrict__ C, const float* __restrict__ Rp, int M, int N, int K)
{
    extern __shared__ char smem_raw[];
    uint32_t sbase = smem_u32(smem_raw);
    const int tid = threadIdx.x, wid = tid >> 5, lane = tid & 31;
    const int bm = blockIdx.y * 128, bn = blockIdx.x * 128;
    const int warp_m = (wid >> 2) * 64;        // 0 or 64
    const int warp_n = (wid & 3) * 32;         // 0,32,64,96
    const int NCH = K / GBK;

    float acc[4][4][4];
    #pragma unroll
    for (int i = 0; i < 4; i++)
        #pragma unroll
        for (int n = 0; n < 4; n++)
            #pragma unroll
            for (int e = 0; e < 4; e++) acc[i][n][e] = 0.0f;

    // lane-dependent ldmatrix address components
    const int arow = lane & 15;                         // A: rows m0..m0+15
    const int acol = (lane >> 4) << 3;                  // A: k-half select
    const int brow = ((lane >> 4) << 3) + (lane & 7);   // B: n within 16
    const int bcol = ((lane >> 3) & 1) << 3;            // B: k-half select

    // prologue: stages 0..2 = chunks 0..2
    #pragma unroll
    for (int p = 0; p < 3; p++) {
        uint32_t sb = sbase + p * STG_BYTES;
        ld_mat32(sb,                 A,  bm, p * GBK, K, tid);
        ld_mat32(sb + MAT_BYTES,     Bh, bn, p * GBK, K, tid);
        ld_mat32(sb + 2 * MAT_BYTES, Bl, bn, p * GBK, K, tid);
        asm volatile("cp.async.commit_group;\n" ::: "memory");
    }

    for (int j = 0; j < NCH; j++) {
        asm volatile("cp.async.wait_group 2;\n" ::: "memory");
        __syncthreads();

        // prefetch chunk j+3 into stage (j+3)%4 (last consumed at j-1; safe after sync)
        if (j + 3 < NCH) {
            uint32_t sb = sbase + ((j + 3) % NSTAGE) * STG_BYTES;
            int k0 = (j + 3) * GBK;
            ld_mat32(sb,                 A,  bm, k0, K, tid);
            ld_mat32(sb + MAT_BYTES,     Bh, bn, k0, K, tid);
            ld_mat32(sb + 2 * MAT_BYTES, Bl, bn, k0, K, tid);
        }
        asm volatile("cp.async.commit_group;\n" ::: "memory");

        uint32_t sb = sbase + (j % NSTAGE) * STG_BYTES;
        #pragma unroll
        for (int ks = 0; ks < 2; ks++) {
            const int k0 = ks * 16;
            uint32_t af[4][4], bhf[2][4], blf[2][4];
            #pragma unroll
            for (int i = 0; i < 4; i++) {
                uint32_t off = (uint32_t)((warp_m + i * 16 + arow) * ROW_B + (k0 + acol) * 2);
                ldsm4(af[i], sb + off);
            }
            #pragma unroll
            for (int jn = 0; jn < 2; jn++) {
                uint32_t off = (uint32_t)((warp_n + jn * 16 + brow) * ROW_B + (k0 + bcol) * 2);
                ldsm4(bhf[jn], sb + MAT_BYTES + off);
                ldsm4(blf[jn], sb + 2 * MAT_BYTES + off);
            }
            #pragma unroll
            for (int i = 0; i < 4; i++) {
                #pragma unroll
                for (int n = 0; n < 4; n++) {
                    uint32_t bh0 = bhf[n >> 1][(n & 1) * 2], bh1 = bhf[n >> 1][(n & 1) * 2 + 1];
                    uint32_t bl0 = blf[n >> 1][(n & 1) * 2], bl1 = blf[n >> 1][(n & 1) * 2 + 1];
                    mma16816(acc[i][n], af[i], bh0, bh1);
                    mma16816(acc[i][n], af[i], bl0, bl1);
                }
            }
        }
    }

    // epilogue: thread holds rows r0, r0+8; cols 2*(lane%4)
    #pragma unroll
    for (int i = 0; i < 4; i++) {
        int r0 = bm + warp_m + i * 16 + (lane >> 2);
        #pragma unroll
        for (int n = 0; n < 4; n++) {
            int col = bn + warp_n + n * 8 + (lane & 3) * 2;
            float2 u0 = make_float2(acc[i][n][0], acc[i][n][1]);
            float2 u1 = make_float2(acc[i][n][2], acc[i][n][3]);
            size_t o0 = (size_t)r0 * N + col;
            size_t o1 = (size_t)(r0 + 8) * N + col;
            if (Rp) {
                float2 q0 = *(const float2*)(Rp + o0);
                float2 q1 = *(const float2*)(Rp + o1);
                u0.x += q0.x; u0.y += q0.y; u1.x += q1.x; u1.y += q1.y;
            }
            *(float2*)(C + o0) = u0;
            *(float2*)(C + o1) = u1;
        }
    }
}

// ---------------- xp: [B,33] = x_main @ W_xp^T, 8 rows/block ----------------
__global__ __launch_bounds__(256) void xp_kernel(const float* __restrict__ W_xp) {
    __shared__ float sx[8][256];
    __shared__ float sw[33][256];
    int tid = threadIdx.x, w = tid >> 5, lid = tid & 31;
    int b0 = blockIdx.x * 8;
    float acc[40];
    #pragma unroll
    for (int i = 0; i < 40; i++) acc[i] = 0.0f;

    for (int kc = 0; kc < D_INNER; kc += 256) {
        #pragma unroll
        for (int i = 0; i < 2; i++) {
            int idx = i * 256 + tid;               // < 512
            int r = idx >> 6, c = (idx & 63) << 2;
            *(float4*)&sx[r][c] =
                *(const float4*)(g_xz + (size_t)(b0 + r) * (2 * D_INNER) + kc + c);
        }
        #pragma unroll
        for (int i = 0; i < 9; i++) {
            int idx = i * 256 + tid;
            if (idx < 33 * 64) {
                int r = idx >> 6, c = (idx & 63) << 2;
                *(float4*)&sw[r][c] = *(const float4*)(W_xp + (size_t)r * D_INNER + kc + c);
            }
        }
        __syncthreads();
        #pragma unroll
        for (int jj = 0; jj < 5; jj++) {
            int j = w + jj * 8;
            if (j < 33) {
                #pragma unroll
                for (int kk = 0; kk < 8; kk++) {
                    float wv = sw[j][kk * 32 + lid];
                    #pragma unroll
                    for (int r = 0; r < 8; r++)
                        acc[jj * 8 + r] = fmaf(sx[r][kk * 32 + lid], wv, acc[jj * 8 + r]);
                }
            }
        }
        __syncthreads();
    }
    #pragma unroll
    for (int jj = 0; jj < 5; jj++) {
        int j = w + jj * 8;
        #pragma unroll
        for (int r = 0; r < 8; r++) {
            float a = acc[jj * 8 + r];
            #pragma unroll
            for (int o = 16; o; o >>= 1) a += __shfl_xor_sync(0xffffffffu, a, o);
            if (lid == 0 && j < 33) g_bcd[(size_t)(b0 + r) * 33 + j] = a;
        }
    }
}

// ---------------- elementwise SSM: thread per (b,d), B/C/delta via smem ------
__global__ __launch_bounds__(256) void ssm2_kernel(const float* __restrict__ h,
                                                   const float* __restrict__ dt_bias,
                                                   const float* __restrict__ Dp,
                                                   float* __restrict__ h_new) {
    int i = blockIdx.x * 256 + threadIdx.x;        // < BATCH*D_INNER
    int b = i >> 12;                               // all threads in block share b
    int d = i & (D_INNER - 1);

    __shared__ float s_bc[33];
    if (threadIdx.x < 33) s_bc[threadIdx.x] = g_bcd[(size_t)b * 33 + threadIdx.x];
    __syncthreads();

    float xm = g_xz[(size_t)b * (2 * D_INNER) + d];
    float z  = g_xz[(size_t)b * (2 * D_INNER) + D_INNER + d];
    float t = s_bc[32] + dt_bias[d];
    float dlt = (t > 20.0f) ? t : log1pf(__expf(t));
    size_t off = (size_t)i * D_STATE;
    const float4* hr = (const float4*)(h + off);
    float4*       ho = (float4*)(h_new + off);
    const float4* Ar = (const float4*)(g_A + d * D_STATE);
    float acc = 0.0f;
    #pragma unroll
    for (int q = 0; q < 4; q++) {
        float4 hv = hr[q], av = Ar[q];
        float4 o;
        o.x = __expf(-dlt * av.x) * hv.x + dlt * s_bc[4*q + 0] * xm;
        o.y = __expf(-dlt * av.y) * hv.y + dlt * s_bc[4*q + 1] * xm;
        o.z = __expf(-dlt * av.z) * hv.z + dlt * s_bc[4*q + 2] * xm;
        o.w = __expf(-dlt * av.w) * hv.w + dlt * s_bc[4*q + 3] * xm;
        ho[q] = o;
        acc += o.x * s_bc[16 + 4*q + 0] + o.y * s_bc[16 + 4*q + 1]
             + o.z * s_bc[16 + 4*q + 2] + o.w * s_bc[16 + 4*q + 3];
    }
    float y = acc + Dp[d] * xm;
    float sig = 1.0f / (1.0f + __expf(-z));
    g_yg[i] = __float2half(y * z * sig);
}

// ---------------- launch ----------------
extern "C" void kernel_launch(void* const* d_in, const int* in_sizes, int n_in,
                              void* d_out, int out_size) {
    const float* x     = (const float*)d_in[0];
    const float* h     = (const float*)d_in[1];
    const float* W_in  = (const float*)d_in[2];
    const float* W_xp  = (const float*)d_in[3];
    const float* log_A = (const float*)d_in[4];
    const float* dt_b  = (const float*)d_in[5];
    const float* Dp    = (const float*)d_in[6];
    const float* W_out = (const float*)d_in[7];
    const float* gamma = (const float*)d_in[8];
    const float* beta  = (const float*)d_in[9];

    float* y_out = (float*)d_out;                         // [2048, 2048]
    float* h_out = y_out + (size_t)BATCH * D_MODEL;       // [2048, 4096, 16]

    void* p;
    cudaGetSymbolAddress(&p, g_xz);  float* xz = (float*)p;
    cudaGetSymbolAddress(&p, g_xh);  __half* xh  = (__half*)p;
    cudaGetSymbolAddress(&p, g_wih); __half* wih = (__half*)p;
    cudaGetSymbolAddress(&p, g_wil); __half* wil = (__half*)p;
    cudaGetSymbolAddress(&p, g_woh); __half* woh = (__half*)p;
    cudaGetSymbolAddress(&p, g_wol); __half* wol = (__half*)p;
    cudaGetSymbolAddress(&p, g_yg);  __half* yg  = (__half*)p;

    cudaFuncSetAttribute(gemm_mma_kernel, cudaFuncAttributeMaxDynamicSharedMemorySize, GEMM_SMEM);

    expA_kernel<<<(D_INNER * D_STATE + 255) / 256, 256>>>(log_A);

    int n4_wi = (2 * D_INNER * D_MODEL) / 4;
    split_kernel<<<(n4_wi + 255) / 256, 256>>>(W_in, wih, wil, n4_wi);
    int n4_wo = (D_MODEL * D_INNER) / 4;
    split_kernel<<<(n4_wo + 255) / 256, 256>>>(W_out, woh, wol, n4_wo);

    ln_kernel<<<BATCH, 256>>>(x, gamma, beta);

    // GEMM1: xz[B, 8192] = xn @ W_in^T
    gemm_mma_kernel<<<dim3(2 * D_INNER / 128, BATCH / 128), 256, GEMM_SMEM>>>(
        xh, wih, wil, xz, nullptr, BATCH, 2 * D_INNER, D_MODEL);

    xp_kernel<<<BATCH / 8, 256>>>(W_xp);

    ssm2_kernel<<<(BATCH * D_INNER) / 256, 256>>>(h, dt_b, Dp, h_out);

    // GEMM2: y[B, 2048] = y_gated @ W_out^T + x
    gemm_mma_kernel<<<dim3(D_MODEL / 128, BATCH / 128), 256, GEMM_SMEM>>>(
        yg, woh, wol, y_out, x, BATCH, D_MODEL, D_INNER);
}

// round 12
// speedup vs baseline: 3.9467x; 1.4059x over previous
#include <cuda_runtime.h>
#include <cuda_fp16.h>
#include <cstdint>

#define D_MODEL 2048
#define D_STATE 16
#define D_INNER 4096
#define BATCH   2048
#define LN_EPS  1e-5f

// ---------------- scratch (device globals: allocation-free) ----------------
__device__ float g_xz [(size_t)BATCH * 2 * D_INNER];          // 64 MB (x_main | z)
__device__ float g_A  [D_INNER * D_STATE];
__device__ float g_bcd[(size_t)BATCH * 33];                   // B(16) C(16) delta_raw(1)
__device__ __half g_xh [(size_t)BATCH * D_MODEL];             // xn, fp16
__device__ __half g_wi [(size_t)2 * D_INNER * D_MODEL];       // W_in fp16
__device__ __half g_wo [(size_t)D_MODEL * D_INNER];           // W_out fp16
__device__ __half g_yg [(size_t)BATCH * D_INNER];             // y_gated, fp16

// ---------------- helpers ----------------
__device__ __forceinline__ uint32_t smem_u32(const void* p) {
    uint32_t a;
    asm("{ .reg .u64 t; cvta.to.shared.u64 t, %1; cvt.u32.u64 %0, t; }" : "=r"(a) : "l"(p));
    return a;
}
__device__ __forceinline__ void ldsm4(uint32_t (&r)[4], uint32_t addr) {
    asm volatile("ldmatrix.sync.aligned.m8n8.x4.shared.b16 {%0,%1,%2,%3}, [%4];"
        : "=r"(r[0]), "=r"(r[1]), "=r"(r[2]), "=r"(r[3]) : "r"(addr));
}
__device__ __forceinline__ void mma16816(float (&c)[4], const uint32_t (&a)[4],
                                         uint32_t b0, uint32_t b1) {
    asm volatile("mma.sync.aligned.m16n8k16.row.col.f32.f16.f16.f32 "
        "{%0,%1,%2,%3}, {%4,%5,%6,%7}, {%8,%9}, {%0,%1,%2,%3};"
        : "+f"(c[0]), "+f"(c[1]), "+f"(c[2]), "+f"(c[3])
        : "r"(a[0]), "r"(a[1]), "r"(a[2]), "r"(a[3]), "r"(b0), "r"(b1));
}

// ---------------- small kernels ----------------
__global__ void expA_kernel(const float* __restrict__ log_A) {
    int i = blockIdx.x * 256 + threadIdx.x;
    if (i < D_INNER * D_STATE) g_A[i] = expf(log_A[i]);
}

// fp32 -> fp16 convert (weights)
__global__ __launch_bounds__(256) void cvt_kernel(const float* __restrict__ s,
                                                  __half* __restrict__ o, int n4) {
    int i = blockIdx.x * 256 + threadIdx.x;
    if (i >= n4) return;
    float4 v = ((const float4*)s)[i];
    __half2 a, b;
    a.x = __float2half(v.x); a.y = __float2half(v.y);
    b.x = __float2half(v.z); b.y = __float2half(v.w);
    *(__half2*)(o + (size_t)i * 4)     = a;
    *(__half2*)(o + (size_t)i * 4 + 2) = b;
}

// LayerNorm -> single fp16 xn
__global__ __launch_bounds__(256) void ln_kernel(const float* __restrict__ x,
                                                 const float* __restrict__ gamma,
                                                 const float* __restrict__ beta) {
    int b = blockIdx.x, tid = threadIdx.x;
    const float4* xr = (const float4*)(x + (size_t)b * D_MODEL);
    float4 v0 = xr[tid];
    float4 v1 = xr[tid + 256];
    float s = v0.x + v0.y + v0.z + v0.w + v1.x + v1.y + v1.z + v1.w;
    float q = v0.x*v0.x + v0.y*v0.y + v0.z*v0.z + v0.w*v0.w
            + v1.x*v1.x + v1.y*v1.y + v1.z*v1.z + v1.w*v1.w;
    #pragma unroll
    for (int o = 16; o; o >>= 1) {
        s += __shfl_xor_sync(0xffffffffu, s, o);
        q += __shfl_xor_sync(0xffffffffu, q, o);
    }
    __shared__ float rs[8], rq[8];
    int w = tid >> 5, l = tid & 31;
    if (l == 0) { rs[w] = s; rq[w] = q; }
    __syncthreads();
    s = rs[0]+rs[1]+rs[2]+rs[3]+rs[4]+rs[5]+rs[6]+rs[7];
    q = rq[0]+rq[1]+rq[2]+rq[3]+rq[4]+rq[5]+rq[6]+rq[7];
    float mean = s * (1.0f / D_MODEL);
    float var  = q * (1.0f / D_MODEL) - mean * mean;
    float rstd = rsqrtf(var + LN_EPS);
    const float4* gr = (const float4*)gamma;
    const float4* br = (const float4*)beta;
    float4 g0 = gr[tid], g1 = gr[tid + 256];
    float4 b0 = br[tid], b1 = br[tid + 256];
    size_t base = (size_t)b * D_MODEL;
    __half2 p0, p1, p2, p3;
    p0.x = __float2half((v0.x-mean)*rstd*g0.x + b0.x);
    p0.y = __float2half((v0.y-mean)*rstd*g0.y + b0.y);
    p1.x = __float2half((v0.z-mean)*rstd*g0.z + b0.z);
    p1.y = __float2half((v0.w-mean)*rstd*g0.w + b0.w);
    p2.x = __float2half((v1.x-mean)*rstd*g1.x + b1.x);
    p2.y = __float2half((v1.y-mean)*rstd*g1.y + b1.y);
    p3.x = __float2half((v1.z-mean)*rstd*g1.z + b1.z);
    p3.y = __float2half((v1.w-mean)*rstd*g1.w + b1.w);
    *(__half2*)(g_xh + base + tid*4)          = p0;
    *(__half2*)(g_xh + base + tid*4 + 2)      = p1;
    *(__half2*)(g_xh + base + 1024 + tid*4)   = p2;
    *(__half2*)(g_xh + base + 1024 + tid*4+2) = p3;
}

// ---------------- mma.sync single-term fp16 NT GEMM ----------------
// C[M,N] = A[M,K]*B[N,K]^T (+R).  CTA: 128x128, BK=32, 8 warps (2x4),
// warp tile 64x32. 5-stage cp.async pipeline.
#define GBK        32
#define ROW_B      80                                  // padded row bytes (40 elems)
#define MAT_BYTES  (128 * ROW_B)                       // 10240
#define STG_BYTES  (2 * MAT_BYTES)                     // 20480 (A|B)
#define NSTAGE     5
#define GEMM_SMEM  (NSTAGE * STG_BYTES)                // 102400

__device__ __forceinline__ void ld_mat32(uint32_t dst, const __half* __restrict__ G,
                                         int rb, int k0, int K, int tid) {
    #pragma unroll
    for (int i = 0; i < 2; i++) {
        int c = tid + i * 256;                 // 0..511
        int row = c >> 2, kc = c & 3;
        uint32_t d = dst + (uint32_t)(row * ROW_B + kc * 16);
        const __half* s = G + (size_t)(rb + row) * K + k0 + kc * 8;
        asm volatile("cp.async.cg.shared.global [%0], [%1], 16;\n" :: "r"(d), "l"(s) : "memory");
    }
}

__global__ __launch_bounds__(256) void gemm_mma_kernel(
    const __half* __restrict__ A, const __half* __restrict__ B,
    float* __restrict__ C, const float* __restrict__ Rp, int M, int N, int K)
{
    extern __shared__ char smem_raw[];
    uint32_t sbase = smem_u32(smem_raw);
    const int tid = threadIdx.x, wid = tid >> 5, lane = tid & 31;
    const int bm = blockIdx.y * 128, bn = blockIdx.x * 128;
    const int warp_m = (wid >> 2) * 64;        // 0 or 64
    const int warp_n = (wid & 3) * 32;         // 0,32,64,96
    const int NCH = K / GBK;

    float acc[4][4][4];
    #pragma unroll
    for (int i = 0; i < 4; i++)
        #pragma unroll
        for (int n = 0; n < 4; n++)
            #pragma unroll
            for (int e = 0; e < 4; e++) acc[i][n][e] = 0.0f;

    // lane-dependent ldmatrix address components
    const int arow = lane & 15;                         // A: rows m0..m0+15
    const int acol = (lane >> 4) << 3;                  // A: k-half select
    const int brow = ((lane >> 4) << 3) + (lane & 7);   // B: n within 16
    const int bcol = ((lane >> 3) & 1) << 3;            // B: k-half select

    // prologue: stages 0..3 = chunks 0..3
    #pragma unroll
    for (int p = 0; p < 4; p++) {
        uint32_t sb = sbase + p * STG_BYTES;
        ld_mat32(sb,             A, bm, p * GBK, K, tid);
        ld_mat32(sb + MAT_BYTES, B, bn, p * GBK, K, tid);
        asm volatile("cp.async.commit_group;\n" ::: "memory");
    }

    for (int j = 0; j < NCH; j++) {
        asm volatile("cp.async.wait_group 3;\n" ::: "memory");
        __syncthreads();

        // prefetch chunk j+4 into stage (j+4)%5 == (j-1)%5 (consumed last iter)
        if (j + 4 < NCH) {
            uint32_t sb = sbase + ((j + 4) % NSTAGE) * STG_BYTES;
            int k0 = (j + 4) * GBK;
            ld_mat32(sb,             A, bm, k0, K, tid);
            ld_mat32(sb + MAT_BYTES, B, bn, k0, K, tid);
        }
        asm volatile("cp.async.commit_group;\n" ::: "memory");

        uint32_t sb = sbase + (j % NSTAGE) * STG_BYTES;
        #pragma unroll
        for (int ks = 0; ks < 2; ks++) {
            const int k0 = ks * 16;
            uint32_t af[4][4], bf[2][4];
            #pragma unroll
            for (int i = 0; i < 4; i++) {
                uint32_t off = (uint32_t)((warp_m + i * 16 + arow) * ROW_B + (k0 + acol) * 2);
                ldsm4(af[i], sb + off);
            }
            #pragma unroll
            for (int jn = 0; jn < 2; jn++) {
                uint32_t off = (uint32_t)((warp_n + jn * 16 + brow) * ROW_B + (k0 + bcol) * 2);
                ldsm4(bf[jn], sb + MAT_BYTES + off);
            }
            #pragma unroll
            for (int i = 0; i < 4; i++) {
                #pragma unroll
                for (int n = 0; n < 4; n++) {
                    mma16816(acc[i][n], af[i],
                             bf[n >> 1][(n & 1) * 2], bf[n >> 1][(n & 1) * 2 + 1]);
                }
            }
        }
    }

    // epilogue: thread holds rows r0, r0+8; cols 2*(lane%4)
    #pragma unroll
    for (int i = 0; i < 4; i++) {
        int r0 = bm + warp_m + i * 16 + (lane >> 2);
        #pragma unroll
        for (int n = 0; n < 4; n++) {
            int col = bn + warp_n + n * 8 + (lane & 3) * 2;
            float2 u0 = make_float2(acc[i][n][0], acc[i][n][1]);
            float2 u1 = make_float2(acc[i][n][2], acc[i][n][3]);
            size_t o0 = (size_t)r0 * N + col;
            size_t o1 = (size_t)(r0 + 8) * N + col;
            if (Rp) {
                float2 q0 = *(const float2*)(Rp + o0);
                float2 q1 = *(const float2*)(Rp + o1);
                u0.x += q0.x; u0.y += q0.y; u1.x += q1.x; u1.y += q1.y;
            }
            *(float2*)(C + o0) = u0;
            *(float2*)(C + o1) = u1;
        }
    }
}

// ---------------- xp: [B,33] = x_main @ W_xp^T, 8 rows/block ----------------
__global__ __launch_bounds__(256) void xp_kernel(const float* __restrict__ W_xp) {
    __shared__ float sx[8][256];
    __shared__ float sw[33][256];
    int tid = threadIdx.x, w = tid >> 5, lid = tid & 31;
    int b0 = blockIdx.x * 8;
    float acc[40];
    #pragma unroll
    for (int i = 0; i < 40; i++) acc[i] = 0.0f;

    for (int kc = 0; kc < D_INNER; kc += 256) {
        #pragma unroll
        for (int i = 0; i < 2; i++) {
            int idx = i * 256 + tid;               // < 512
            int r = idx >> 6, c = (idx & 63) << 2;
            *(float4*)&sx[r][c] =
                *(const float4*)(g_xz + (size_t)(b0 + r) * (2 * D_INNER) + kc + c);
        }
        #pragma unroll
        for (int i = 0; i < 9; i++) {
            int idx = i * 256 + tid;
            if (idx < 33 * 64) {
                int r = idx >> 6, c = (idx & 63) << 2;
                *(float4*)&sw[r][c] = *(const float4*)(W_xp + (size_t)r * D_INNER + kc + c);
            }
        }
        __syncthreads();
        #pragma unroll
        for (int jj = 0; jj < 5; jj++) {
            int j = w + jj * 8;
            if (j < 33) {
                #pragma unroll
                for (int kk = 0; kk < 8; kk++) {
                    float wv = sw[j][kk * 32 + lid];
                    #pragma unroll
                    for (int r = 0; r < 8; r++)
                        acc[jj * 8 + r] = fmaf(sx[r][kk * 32 + lid], wv, acc[jj * 8 + r]);
                }
            }
        }
        __syncthreads();
    }
    #pragma unroll
    for (int jj = 0; jj < 5; jj++) {
        int j = w + jj * 8;
        #pragma unroll
        for (int r = 0; r < 8; r++) {
            float a = acc[jj * 8 + r];
            #pragma unroll
            for (int o = 16; o; o >>= 1) a += __shfl_xor_sync(0xffffffffu, a, o);
            if (lid == 0 && j < 33) g_bcd[(size_t)(b0 + r) * 33 + j] = a;
        }
    }
}

// ---------------- elementwise SSM: thread per (b,d), streaming h ------------
__global__ __launch_bounds__(256) void ssm2_kernel(const float* __restrict__ h,
                                                   const float* __restrict__ dt_bias,
                                                   const float* __restrict__ Dp,
                                                   float* __restrict__ h_new) {
    int i = blockIdx.x * 256 + threadIdx.x;        // < BATCH*D_INNER
    int b = i >> 12;                               // all threads in block share b
    int d = i & (D_INNER - 1);

    __shared__ float s_bc[33];
    if (threadIdx.x < 33) s_bc[threadIdx.x] = g_bcd[(size_t)b * 33 + threadIdx.x];
    __syncthreads();

    float xm = g_xz[(size_t)b * (2 * D_INNER) + d];
    float z  = g_xz[(size_t)b * (2 * D_INNER) + D_INNER + d];
    float t = s_bc[32] + dt_bias[d];
    float dlt = (t > 20.0f) ? t : log1pf(__expf(t));
    size_t off = (size_t)i * D_STATE;
    const float4* hr = (const float4*)(h + off);
    float4*       ho = (float4*)(h_new + off);
    const float4* Ar = (const float4*)(g_A + d * D_STATE);
    float acc = 0.0f;
    #pragma unroll
    for (int q = 0; q < 4; q++) {
        float4 hv = __ldcs(hr + q);                // streaming: no reuse
        float4 av = Ar[q];
        float4 o;
        o.x = __expf(-dlt * av.x) * hv.x + dlt * s_bc[4*q + 0] * xm;
        o.y = __expf(-dlt * av.y) * hv.y + dlt * s_bc[4*q + 1] * xm;
        o.z = __expf(-dlt * av.z) * hv.z + dlt * s_bc[4*q + 2] * xm;
        o.w = __expf(-dlt * av.w) * hv.w + dlt * s_bc[4*q + 3] * xm;
        __stcs(ho + q, o);                         // streaming store
        acc += o.x * s_bc[16 + 4*q + 0] + o.y * s_bc[16 + 4*q + 1]
             + o.z * s_bc[16 + 4*q + 2] + o.w * s_bc[16 + 4*q + 3];
    }
    float y = acc + Dp[d] * xm;
    float sig = 1.0f / (1.0f + __expf(-z));
    g_yg[i] = __float2half(y * z * sig);
}

// ---------------- launch ----------------
extern "C" void kernel_launch(void* const* d_in, const int* in_sizes, int n_in,
                              void* d_out, int out_size) {
    const float* x     = (const float*)d_in[0];
    const float* h     = (const float*)d_in[1];
    const float* W_in  = (const float*)d_in[2];
    const float* W_xp  = (const float*)d_in[3];
    const float* log_A = (const float*)d_in[4];
    const float* dt_b  = (const float*)d_in[5];
    const float* Dp    = (const float*)d_in[6];
    const float* W_out = (const float*)d_in[7];
    const float* gamma = (const float*)d_in[8];
    const float* beta  = (const float*)d_in[9];

    float* y_out = (float*)d_out;                         // [2048, 2048]
    float* h_out = y_out + (size_t)BATCH * D_MODEL;       // [2048, 4096, 16]

    void* p;
    cudaGetSymbolAddress(&p, g_xz);  float* xz = (float*)p;
    cudaGetSymbolAddress(&p, g_xh);  __half* xh = (__half*)p;
    cudaGetSymbolAddress(&p, g_wi);  __half* wi = (__half*)p;
    cudaGetSymbolAddress(&p, g_wo);  __half* wo = (__half*)p;
    cudaGetSymbolAddress(&p, g_yg);  __half* yg = (__half*)p;

    cudaFuncSetAttribute(gemm_mma_kernel, cudaFuncAttributeMaxDynamicSharedMemorySize, GEMM_SMEM);

    expA_kernel<<<(D_INNER * D_STATE + 255) / 256, 256>>>(log_A);

    int n4_wi = (2 * D_INNER * D_MODEL) / 4;
    cvt_kernel<<<(n4_wi + 255) / 256, 256>>>(W_in, wi, n4_wi);
    int n4_wo = (D_MODEL * D_INNER) / 4;
    cvt_kernel<<<(n4_wo + 255) / 256, 256>>>(W_out, wo, n4_wo);

    ln_kernel<<<BATCH, 256>>>(x, gamma, beta);

    // GEMM1: xz[B, 8192] = xn @ W_in^T
    gemm_mma_kernel<<<dim3(2 * D_INNER / 128, BATCH / 128), 256, GEMM_SMEM>>>(
        xh, wi, xz, nullptr, BATCH, 2 * D_INNER, D_MODEL);

    xp_kernel<<<BATCH / 8, 256>>>(W_xp);

    ssm2_kernel<<<(BATCH * D_INNER) / 256, 256>>>(h, dt_b, Dp, h_out);

    // GEMM2: y[B, 2048] = y_gated @ W_out^T + x
    gemm_mma_kernel<<<dim3(D_MODEL / 128, BATCH / 128), 256, GEMM_SMEM>>>(
        yg, wo, y_out, x, BATCH, D_MODEL, D_INNER);
}

// round 14
// speedup vs baseline: 4.2545x; 1.0780x over previous
#include <cuda_runtime.h>
#include <cuda_fp16.h>
#include <cstdint>

#define D_MODEL 2048
#define D_STATE 16
#define D_INNER 4096
#define BATCH   2048
#define LN_EPS  1e-5f

// ---------------- scratch (device globals: allocation-free) ----------------
__device__ float g_xz [(size_t)BATCH * 2 * D_INNER];          // 64 MB (x_main | z)
__device__ float g_A  [D_INNER * D_STATE];
__device__ float g_bcd[(size_t)BATCH * 33];                   // B(16) C(16) delta_raw(1)
__device__ __half g_xh [(size_t)BATCH * D_MODEL];             // xn, fp16
__device__ __half g_wi [(size_t)2 * D_INNER * D_MODEL];       // W_in fp16
__device__ __half g_wo [(size_t)D_MODEL * D_INNER];           // W_out fp16
__device__ __half g_yg [(size_t)BATCH * D_INNER];             // y_gated, fp16

// ---------------- helpers ----------------
__device__ __forceinline__ uint32_t smem_u32(const void* p) {
    uint32_t a;
    asm("{ .reg .u64 t; cvta.to.shared.u64 t, %1; cvt.u32.u64 %0, t; }" : "=r"(a) : "l"(p));
    return a;
}
__device__ __forceinline__ void ldsm4(uint32_t (&r)[4], uint32_t addr) {
    asm volatile("ldmatrix.sync.aligned.m8n8.x4.shared.b16 {%0,%1,%2,%3}, [%4];"
        : "=r"(r[0]), "=r"(r[1]), "=r"(r[2]), "=r"(r[3]) : "r"(addr));
}
__device__ __forceinline__ void mma16816(float (&c)[4], const uint32_t (&a)[4],
                                         uint32_t b0, uint32_t b1) {
    asm volatile("mma.sync.aligned.m16n8k16.row.col.f32.f16.f16.f32 "
        "{%0,%1,%2,%3}, {%4,%5,%6,%7}, {%8,%9}, {%0,%1,%2,%3};"
        : "+f"(c[0]), "+f"(c[1]), "+f"(c[2]), "+f"(c[3])
        : "r"(a[0]), "r"(a[1]), "r"(a[2]), "r"(a[3]), "r"(b0), "r"(b1));
}

// ---------------- small kernels ----------------
__global__ void expA_kernel(const float* __restrict__ log_A) {
    int i = blockIdx.x * 256 + threadIdx.x;
    if (i < D_INNER * D_STATE) g_A[i] = expf(log_A[i]);
}

// fp32 -> fp16 convert (weights)
__global__ __launch_bounds__(256) void cvt_kernel(const float* __restrict__ s,
                                                  __half* __restrict__ o, int n4) {
    int i = blockIdx.x * 256 + threadIdx.x;
    if (i >= n4) return;
    float4 v = ((const float4*)s)[i];
    __half2 a, b;
    a.x = __float2half(v.x); a.y = __float2half(v.y);
    b.x = __float2half(v.z); b.y = __float2half(v.w);
    *(__half2*)(o + (size_t)i * 4)     = a;
    *(__half2*)(o + (size_t)i * 4 + 2) = b;
}

// LayerNorm -> single fp16 xn
__global__ __launch_bounds__(256) void ln_kernel(const float* __restrict__ x,
                                                 const float* __restrict__ gamma,
                                                 const float* __restrict__ beta) {
    int b = blockIdx.x, tid = threadIdx.x;
    const float4* xr = (const float4*)(x + (size_t)b * D_MODEL);
    float4 v0 = xr[tid];
    float4 v1 = xr[tid + 256];
    float s = v0.x + v0.y + v0.z + v0.w + v1.x + v1.y + v1.z + v1.w;
    float q = v0.x*v0.x + v0.y*v0.y + v0.z*v0.z + v0.w*v0.w
            + v1.x*v1.x + v1.y*v1.y + v1.z*v1.z + v1.w*v1.w;
    #pragma unroll
    for (int o = 16; o; o >>= 1) {
        s += __shfl_xor_sync(0xffffffffu, s, o);
        q += __shfl_xor_sync(0xffffffffu, q, o);
    }
    __shared__ float rs[8], rq[8];
    int w = tid >> 5, l = tid & 31;
    if (l == 0) { rs[w] = s; rq[w] = q; }
    __syncthreads();
    s = rs[0]+rs[1]+rs[2]+rs[3]+rs[4]+rs[5]+rs[6]+rs[7];
    q = rq[0]+rq[1]+rq[2]+rq[3]+rq[4]+rq[5]+rq[6]+rq[7];
    float mean = s * (1.0f / D_MODEL);
    float var  = q * (1.0f / D_MODEL) - mean * mean;
    float rstd = rsqrtf(var + LN_EPS);
    const float4* gr = (const float4*)gamma;
    const float4* br = (const float4*)beta;
    float4 g0 = gr[tid], g1 = gr[tid + 256];
    float4 b0 = br[tid], b1 = br[tid + 256];
    size_t base = (size_t)b * D_MODEL;
    __half2 p0, p1, p2, p3;
    p0.x = __float2half((v0.x-mean)*rstd*g0.x + b0.x);
    p0.y = __float2half((v0.y-mean)*rstd*g0.y + b0.y);
    p1.x = __float2half((v0.z-mean)*rstd*g0.z + b0.z);
    p1.y = __float2half((v0.w-mean)*rstd*g0.w + b0.w);
    p2.x = __float2half((v1.x-mean)*rstd*g1.x + b1.x);
    p2.y = __float2half((v1.y-mean)*rstd*g1.y + b1.y);
    p3.x = __float2half((v1.z-mean)*rstd*g1.z + b1.z);
    p3.y = __float2half((v1.w-mean)*rstd*g1.w + b1.w);
    *(__half2*)(g_xh + base + tid*4)          = p0;
    *(__half2*)(g_xh + base + tid*4 + 2)      = p1;
    *(__half2*)(g_xh + base + 1024 + tid*4)   = p2;
    *(__half2*)(g_xh + base + 1024 + tid*4+2) = p3;
}

// ---------------- mma.sync fp16 NT GEMM, 64x64 warp tiles ----------------
// C[M,N] = A[M,K]*B[N,K]^T (+R).  CTA: 128x128, BK=32, 4 warps (2x2),
// warp tile 64x64. 4-stage cp.async pipeline, 2 CTAs/SM.
#define GBK        32
#define ROW_B      80                                  // padded row bytes (40 elems)
#define MAT_BYTES  (128 * ROW_B)                       // 10240
#define STG_BYTES  (2 * MAT_BYTES)                     // 20480 (A|B)
#define NSTAGE     4
#define GEMM_SMEM  (NSTAGE * STG_BYTES)                // 81920

__device__ __forceinline__ void ld_mat32(uint32_t dst, const __half* __restrict__ G,
                                         int rb, int k0, int K, int tid) {
    #pragma unroll
    for (int i = 0; i < 4; i++) {
        int c = tid + i * 128;                 // 0..511
        int row = c >> 2, kc = c & 3;
        uint32_t d = dst + (uint32_t)(row * ROW_B + kc * 16);
        const __half* s = G + (size_t)(rb + row) * K + k0 + kc * 8;
        asm volatile("cp.async.cg.shared.global [%0], [%1], 16;\n" :: "r"(d), "l"(s) : "memory");
    }
}

__global__ __launch_bounds__(128, 2) void gemm_mma_kernel(
    const __half* __restrict__ A, const __half* __restrict__ B,
    float* __restrict__ C, const float* __restrict__ Rp, int M, int N, int K)
{
    extern __shared__ char smem_raw[];
    uint32_t sbase = smem_u32(smem_raw);
    const int tid = threadIdx.x, wid = tid >> 5, lane = tid & 31;
    const int bm = blockIdx.y * 128, bn = blockIdx.x * 128;
    const int warp_m = (wid >> 1) * 64;        // 0 or 64
    const int warp_n = (wid & 1) * 64;         // 0 or 64
    const int NCH = K / GBK;

    float acc[4][8][4];
    #pragma unroll
    for (int i = 0; i < 4; i++)
        #pragma unroll
        for (int n = 0; n < 8; n++)
            #pragma unroll
            for (int e = 0; e < 4; e++) acc[i][n][e] = 0.0f;

    // lane-dependent ldmatrix address components
    const int arow = lane & 15;                         // A: rows m0..m0+15
    const int acol = (lane >> 4) << 3;                  // A: k-half select
    const int brow = ((lane >> 4) << 3) + (lane & 7);   // B: n within 16
    const int bcol = ((lane >> 3) & 1) << 3;            // B: k-half select

    // prologue: stages 0..2 = chunks 0..2
    #pragma unroll
    for (int p = 0; p < 3; p++) {
        uint32_t sb = sbase + p * STG_BYTES;
        ld_mat32(sb,             A, bm, p * GBK, K, tid);
        ld_mat32(sb + MAT_BYTES, B, bn, p * GBK, K, tid);
        asm volatile("cp.async.commit_group;\n" ::: "memory");
    }

    for (int j = 0; j < NCH; j++) {
        asm volatile("cp.async.wait_group 2;\n" ::: "memory");
        __syncthreads();

        // prefetch chunk j+3 into stage (j+3)%4 == (j-1)%4 (consumed last iter)
        if (j + 3 < NCH) {
            uint32_t sb = sbase + ((j + 3) % NSTAGE) * STG_BYTES;
            int k0 = (j + 3) * GBK;
            ld_mat32(sb,             A, bm, k0, K, tid);
            ld_mat32(sb + MAT_BYTES, B, bn, k0, K, tid);
        }
        asm volatile("cp.async.commit_group;\n" ::: "memory");

        uint32_t sb = sbase + (j % NSTAGE) * STG_BYTES;
        #pragma unroll
        for (int ks = 0; ks < 2; ks++) {
            const int k0 = ks * 16;
            uint32_t af[4][4], bf[4][4];
            #pragma unroll
            for (int i = 0; i < 4; i++) {
                uint32_t off = (uint32_t)((warp_m + i * 16 + arow) * ROW_B + (k0 + acol) * 2);
                ldsm4(af[i], sb + off);
            }
            #pragma unroll
            for (int jn = 0; jn < 4; jn++) {
                uint32_t off = (uint32_t)((warp_n + jn * 16 + brow) * ROW_B + (k0 + bcol) * 2);
                ldsm4(bf[jn], sb + MAT_BYTES + off);
            }
            #pragma unroll
            for (int i = 0; i < 4; i++) {
                #pragma unroll
                for (int n = 0; n < 8; n++) {
                    mma16816(acc[i][n], af[i],
                             bf[n >> 1][(n & 1) * 2], bf[n >> 1][(n & 1) * 2 + 1]);
                }
            }
        }
    }

    // epilogue: thread holds rows r0, r0+8; cols 2*(lane%4)
    #pragma unroll
    for (int i = 0; i < 4; i++) {
        int r0 = bm + warp_m + i * 16 + (lane >> 2);
        #pragma unroll
        for (int n = 0; n < 8; n++) {
            int col = bn + warp_n + n * 8 + (lane & 3) * 2;
            float2 u0 = make_float2(acc[i][n][0], acc[i][n][1]);
            float2 u1 = make_float2(acc[i][n][2], acc[i][n][3]);
            size_t o0 = (size_t)r0 * N + col;
            size_t o1 = (size_t)(r0 + 8) * N + col;
            if (Rp) {
                float2 q0 = *(const float2*)(Rp + o0);
                float2 q1 = *(const float2*)(Rp + o1);
                u0.x += q0.x; u0.y += q0.y; u1.x += q1.x; u1.y += q1.y;
            }
            *(float2*)(C + o0) = u0;
            *(float2*)(C + o1) = u1;
        }
    }
}

// ---------------- xp: [B,33] = x_main @ W_xp^T, 16 rows/block ----------------
// k-chunk 128; W_xp L2 traffic = 128 blocks * 540KB = 68 MB.
__global__ __launch_bounds__(256) void xp_kernel(const float* __restrict__ W_xp) {
    __shared__ float sx[16][128];
    __shared__ float sw[33][128];
    int tid = threadIdx.x, w = tid >> 5, lid = tid & 31;
    int b0 = blockIdx.x * 16;
    float acc[5][16];
    #pragma unroll
    for (int jj = 0; jj < 5; jj++)
        #pragma unroll
        for (int r = 0; r < 16; r++) acc[jj][r] = 0.0f;

    for (int kc = 0; kc < D_INNER; kc += 128) {
        {   // load 16 x 128 x_main block (512 float4)
            #pragma unroll
            for (int i = 0; i < 2; i++) {
                int idx = i * 256 + tid;           // < 512
                int r = idx >> 5, c = (idx & 31) << 2;
                *(float4*)&sx[r][c] =
                    *(const float4*)(g_xz + (size_t)(b0 + r) * (2 * D_INNER) + kc + c);
            }
        }
        {   // load 33 x 128 W_xp block (1056 float4)
            #pragma unroll
            for (int i = 0; i < 5; i++) {
                int idx = i * 256 + tid;
                if (idx < 33 * 32) {
                    int r = idx >> 5, c = (idx & 31) << 2;
                    *(float4*)&sw[r][c] = *(const float4*)(W_xp + (size_t)r * D_INNER + kc + c);
                }
            }
        }
        __syncthreads();
        #pragma unroll
        for (int jj = 0; jj < 5; jj++) {
            int j = w + jj * 8;
            if (j < 33) {
                #pragma unroll
                for (int kk = 0; kk < 4; kk++) {
                    float wv = sw[j][kk * 32 + lid];
                    #pragma unroll
                    for (int r = 0; r < 16; r++)
                        acc[jj][r] = fmaf(sx[r][kk * 32 + lid], wv, acc[jj][r]);
                }
            }
        }
        __syncthreads();
    }
    #pragma unroll
    for (int jj = 0; jj < 5; jj++) {
        int j = w + jj * 8;
        #pragma unroll
        for (int r = 0; r < 16; r++) {
            float a = acc[jj][r];
            #pragma unroll
            for (int o = 16; o; o >>= 1) a += __shfl_xor_sync(0xffffffffu, a, o);
            if (lid == 0 && j < 33) g_bcd[(size_t)(b0 + r) * 33 + j] = a;
        }
    }
}

// ---------------- elementwise SSM: thread per (b,d), streaming h ------------
__global__ __launch_bounds__(256) void ssm2_kernel(const float* __restrict__ h,
                                                   const float* __restrict__ dt_bias,
                                                   const float* __restrict__ Dp,
                                                   float* __restrict__ h_new) {
    int i = blockIdx.x * 256 + threadIdx.x;        // < BATCH*D_INNER
    int b = i >> 12;                               // all threads in block share b
    int d = i & (D_INNER - 1);

    __shared__ float s_bc[33];
    if (threadIdx.x < 33) s_bc[threadIdx.x] = g_bcd[(size_t)b * 33 + threadIdx.x];
    __syncthreads();

    float xm = g_xz[(size_t)b * (2 * D_INNER) + d];
    float z  = g_xz[(size_t)b * (2 * D_INNER) + D_INNER + d];
    float t = s_bc[32] + dt_bias[d];
    float dlt = (t > 20.0f) ? t : log1pf(__expf(t));
    size_t off = (size_t)i * D_STATE;
    const float4* hr = (const float4*)(h + off);
    float4*       ho = (float4*)(h_new + off);
    const float4* Ar = (const float4*)(g_A + d * D_STATE);
    float acc = 0.0f;
    #pragma unroll
    for (int q = 0; q < 4; q++) {
        float4 hv = __ldcs(hr + q);                // streaming: no reuse
        float4 av = Ar[q];
        float4 o;
        o.x = __expf(-dlt * av.x) * hv.x + dlt * s_bc[4*q + 0] * xm;
        o.y = __expf(-dlt * av.y) * hv.y + dlt * s_bc[4*q + 1] * xm;
        o.z = __expf(-dlt * av.z) * hv.z + dlt * s_bc[4*q + 2] * xm;
        o.w = __expf(-dlt * av.w) * hv.w + dlt * s_bc[4*q + 3] * xm;
        __stcs(ho + q, o);                         // streaming store
        acc += o.x * s_bc[16 + 4*q + 0] + o.y * s_bc[16 + 4*q + 1]
             + o.z * s_bc[16 + 4*q + 2] + o.w * s_bc[16 + 4*q + 3];
    }
    float y = acc + Dp[d] * xm;
    float sig = 1.0f / (1.0f + __expf(-z));
    g_yg[i] = __float2half(y * z * sig);
}

// ---------------- launch ----------------
extern "C" void kernel_launch(void* const* d_in, const int* in_sizes, int n_in,
                              void* d_out, int out_size) {
    const float* x     = (const float*)d_in[0];
    const float* h     = (const float*)d_in[1];
    const float* W_in  = (const float*)d_in[2];
    const float* W_xp  = (const float*)d_in[3];
    const float* log_A = (const float*)d_in[4];
    const float* dt_b  = (const float*)d_in[5];
    const float* Dp    = (const float*)d_in[6];
    const float* W_out = (const float*)d_in[7];
    const float* gamma = (const float*)d_in[8];
    const float* beta  = (const float*)d_in[9];

    float* y_out = (float*)d_out;                         // [2048, 2048]
    float* h_out = y_out + (size_t)BATCH * D_MODEL;       // [2048, 4096, 16]

    void* p;
    cudaGetSymbolAddress(&p, g_xz);  float* xz = (float*)p;
    cudaGetSymbolAddress(&p, g_xh);  __half* xh = (__half*)p;
    cudaGetSymbolAddress(&p, g_wi);  __half* wi = (__half*)p;
    cudaGetSymbolAddress(&p, g_wo);  __half* wo = (__half*)p;
    cudaGetSymbolAddress(&p, g_yg);  __half* yg = (__half*)p;

    cudaFuncSetAttribute(gemm_mma_kernel, cudaFuncAttributeMaxDynamicSharedMemorySize, GEMM_SMEM);

    expA_kernel<<<(D_INNER * D_STATE + 255) / 256, 256>>>(log_A);

    int n4_wi = (2 * D_INNER * D_MODEL) / 4;
    cvt_kernel<<<(n4_wi + 255) / 256, 256>>>(W_in, wi, n4_wi);
    int n4_wo = (D_MODEL * D_INNER) / 4;
    cvt_kernel<<<(n4_wo + 255) / 256, 256>>>(W_out, wo, n4_wo);

    ln_kernel<<<BATCH, 256>>>(x, gamma, beta);

    // GEMM1: xz[B, 8192] = xn @ W_in^T
    gemm_mma_kernel<<<dim3(2 * D_INNER / 128, BATCH / 128), 128, GEMM_SMEM>>>(
        xh, wi, xz, nullptr, BATCH, 2 * D_INNER, D_MODEL);

    xp_kernel<<<BATCH / 16, 256>>>(W_xp);

    ssm2_kernel<<<(BATCH * D_INNER) / 256, 256>>>(h, dt_b, Dp, h_out);

    // GEMM2: y[B, 2048] = y_gated @ W_out^T + x
    gemm_mma_kernel<<<dim3(D_MODEL / 128, BATCH / 128), 128, GEMM_SMEM>>>(
        yg, wo, y_out, x, BATCH, D_MODEL, D_INNER);
}

// round 15
// speedup vs baseline: 4.5936x; 1.0797x over previous
#include <cuda_runtime.h>
#include <cuda_fp16.h>
#include <cstdint>

#define D_MODEL 2048
#define D_STATE 16
#define D_INNER 4096
#define BATCH   2048
#define LN_EPS  1e-5f

// ---------------- scratch (device globals: allocation-free) ----------------
__device__ float g_xz [(size_t)BATCH * 2 * D_INNER];          // 64 MB (x_main | z)
__device__ float g_A  [D_INNER * D_STATE];
__device__ float g_bcd[(size_t)BATCH * 33];                   // B(16) C(16) delta_raw(1)
__device__ __half g_xh [(size_t)BATCH * D_MODEL];             // xn, fp16
__device__ __half g_wi [(size_t)2 * D_INNER * D_MODEL];       // W_in fp16
__device__ __half g_wo [(size_t)D_MODEL * D_INNER];           // W_out fp16
__device__ __half g_yg [(size_t)BATCH * D_INNER];             // y_gated, fp16

// ---------------- helpers ----------------
__device__ __forceinline__ uint32_t smem_u32(const void* p) {
    uint32_t a;
    asm("{ .reg .u64 t; cvta.to.shared.u64 t, %1; cvt.u32.u64 %0, t; }" : "=r"(a) : "l"(p));
    return a;
}
__device__ __forceinline__ void ldsm4(uint32_t (&r)[4], uint32_t addr) {
    asm volatile("ldmatrix.sync.aligned.m8n8.x4.shared.b16 {%0,%1,%2,%3}, [%4];"
        : "=r"(r[0]), "=r"(r[1]), "=r"(r[2]), "=r"(r[3]) : "r"(addr));
}
__device__ __forceinline__ void mma16816(float (&c)[4], const uint32_t (&a)[4],
                                         uint32_t b0, uint32_t b1) {
    asm volatile("mma.sync.aligned.m16n8k16.row.col.f32.f16.f16.f32 "
        "{%0,%1,%2,%3}, {%4,%5,%6,%7}, {%8,%9}, {%0,%1,%2,%3};"
        : "+f"(c[0]), "+f"(c[1]), "+f"(c[2]), "+f"(c[3])
        : "r"(a[0]), "r"(a[1]), "r"(a[2]), "r"(a[3]), "r"(b0), "r"(b1));
}

// ---------------- small kernels ----------------
__global__ void expA_kernel(const float* __restrict__ log_A) {
    int i = blockIdx.x * 256 + threadIdx.x;
    if (i < D_INNER * D_STATE) g_A[i] = expf(log_A[i]);
}

// fp32 -> fp16 convert (weights)
__global__ __launch_bounds__(256) void cvt_kernel(const float* __restrict__ s,
                                                  __half* __restrict__ o, int n4) {
    int i = blockIdx.x * 256 + threadIdx.x;
    if (i >= n4) return;
    float4 v = ((const float4*)s)[i];
    __half2 a, b;
    a.x = __float2half(v.x); a.y = __float2half(v.y);
    b.x = __float2half(v.z); b.y = __float2half(v.w);
    *(__half2*)(o + (size_t)i * 4)     = a;
    *(__half2*)(o + (size_t)i * 4 + 2) = b;
}

// LayerNorm -> single fp16 xn
__global__ __launch_bounds__(256) void ln_kernel(const float* __restrict__ x,
                                                 const float* __restrict__ gamma,
                                                 const float* __restrict__ beta) {
    int b = blockIdx.x, tid = threadIdx.x;
    const float4* xr = (const float4*)(x + (size_t)b * D_MODEL);
    float4 v0 = xr[tid];
    float4 v1 = xr[tid + 256];
    float s = v0.x + v0.y + v0.z + v0.w + v1.x + v1.y + v1.z + v1.w;
    float q = v0.x*v0.x + v0.y*v0.y + v0.z*v0.z + v0.w*v0.w
            + v1.x*v1.x + v1.y*v1.y + v1.z*v1.z + v1.w*v1.w;
    #pragma unroll
    for (int o = 16; o; o >>= 1) {
        s += __shfl_xor_sync(0xffffffffu, s, o);
        q += __shfl_xor_sync(0xffffffffu, q, o);
    }
    __shared__ float rs[8], rq[8];
    int w = tid >> 5, l = tid & 31;
    if (l == 0) { rs[w] = s; rq[w] = q; }
    __syncthreads();
    s = rs[0]+rs[1]+rs[2]+rs[3]+rs[4]+rs[5]+rs[6]+rs[7];
    q = rq[0]+rq[1]+rq[2]+rq[3]+rq[4]+rq[5]+rq[6]+rq[7];
    float mean = s * (1.0f / D_MODEL);
    float var  = q * (1.0f / D_MODEL) - mean * mean;
    float rstd = rsqrtf(var + LN_EPS);
    const float4* gr = (const float4*)gamma;
    const float4* br = (const float4*)beta;
    float4 g0 = gr[tid], g1 = gr[tid + 256];
    float4 b0 = br[tid], b1 = br[tid + 256];
    size_t base = (size_t)b * D_MODEL;
    __half2 p0, p1, p2, p3;
    p0.x = __float2half((v0.x-mean)*rstd*g0.x + b0.x);
    p0.y = __float2half((v0.y-mean)*rstd*g0.y + b0.y);
    p1.x = __float2half((v0.z-mean)*rstd*g0.z + b0.z);
    p1.y = __float2half((v0.w-mean)*rstd*g0.w + b0.w);
    p2.x = __float2half((v1.x-mean)*rstd*g1.x + b1.x);
    p2.y = __float2half((v1.y-mean)*rstd*g1.y + b1.y);
    p3.x = __float2half((v1.z-mean)*rstd*g1.z + b1.z);
    p3.y = __float2half((v1.w-mean)*rstd*g1.w + b1.w);
    *(__half2*)(g_xh + base + tid*4)          = p0;
    *(__half2*)(g_xh + base + tid*4 + 2)      = p1;
    *(__half2*)(g_xh + base + 1024 + tid*4)   = p2;
    *(__half2*)(g_xh + base + 1024 + tid*4+2) = p3;
}

// ---------------- mma.sync fp16 NT GEMM, 64x64 warp tiles ----------------
// C[M,N] = A[M,K]*B[N,K]^T (+R).  CTA: 128x128, BK=32, 4 warps (2x2),
// warp tile 64x64. 4-stage cp.async pipeline, 2 CTAs/SM.
#define GBK        32
#define ROW_B      80                                  // padded row bytes (40 elems)
#define MAT_BYTES  (128 * ROW_B)                       // 10240
#define STG_BYTES  (2 * MAT_BYTES)                     // 20480 (A|B)
#define NSTAGE     4
#define GEMM_SMEM  (NSTAGE * STG_BYTES)                // 81920

__device__ __forceinline__ void ld_mat32(uint32_t dst, const __half* __restrict__ G,
                                         int rb, int k0, int K, int tid) {
    #pragma unroll
    for (int i = 0; i < 4; i++) {
        int c = tid + i * 128;                 // 0..511
        int row = c >> 2, kc = c & 3;
        uint32_t d = dst + (uint32_t)(row * ROW_B + kc * 16);
        const __half* s = G + (size_t)(rb + row) * K + k0 + kc * 8;
        asm volatile("cp.async.cg.shared.global [%0], [%1], 16;\n" :: "r"(d), "l"(s) : "memory");
    }
}

__global__ __launch_bounds__(128, 2) void gemm_mma_kernel(
    const __half* __restrict__ A, const __half* __restrict__ B,
    float* __restrict__ C, const float* __restrict__ Rp, int M, int N, int K)
{
    extern __shared__ char smem_raw[];
    uint32_t sbase = smem_u32(smem_raw);
    const int tid = threadIdx.x, wid = tid >> 5, lane = tid & 31;
    const int bm = blockIdx.y * 128, bn = blockIdx.x * 128;
    const int warp_m = (wid >> 1) * 64;        // 0 or 64
    const int warp_n = (wid & 1) * 64;         // 0 or 64
    const int NCH = K / GBK;

    float acc[4][8][4];
    #pragma unroll
    for (int i = 0; i < 4; i++)
        #pragma unroll
        for (int n = 0; n < 8; n++)
            #pragma unroll
            for (int e = 0; e < 4; e++) acc[i][n][e] = 0.0f;

    // lane-dependent ldmatrix address components
    const int arow = lane & 15;                         // A: rows m0..m0+15
    const int acol = (lane >> 4) << 3;                  // A: k-half select
    const int brow = ((lane >> 4) << 3) + (lane & 7);   // B: n within 16
    const int bcol = ((lane >> 3) & 1) << 3;            // B: k-half select

    // prologue: stages 0..2 = chunks 0..2
    #pragma unroll
    for (int p = 0; p < 3; p++) {
        uint32_t sb = sbase + p * STG_BYTES;
        ld_mat32(sb,             A, bm, p * GBK, K, tid);
        ld_mat32(sb + MAT_BYTES, B, bn, p * GBK, K, tid);
        asm volatile("cp.async.commit_group;\n" ::: "memory");
    }

    for (int j = 0; j < NCH; j++) {
        asm volatile("cp.async.wait_group 2;\n" ::: "memory");
        __syncthreads();

        // prefetch chunk j+3 into stage (j+3)%4 == (j-1)%4 (consumed last iter)
        if (j + 3 < NCH) {
            uint32_t sb = sbase + ((j + 3) % NSTAGE) * STG_BYTES;
            int k0 = (j + 3) * GBK;
            ld_mat32(sb,             A, bm, k0, K, tid);
            ld_mat32(sb + MAT_BYTES, B, bn, k0, K, tid);
        }
        asm volatile("cp.async.commit_group;\n" ::: "memory");

        uint32_t sb = sbase + (j % NSTAGE) * STG_BYTES;
        #pragma unroll
        for (int ks = 0; ks < 2; ks++) {
            const int k0 = ks * 16;
            uint32_t af[4][4], bf[4][4];
            #pragma unroll
            for (int i = 0; i < 4; i++) {
                uint32_t off = (uint32_t)((warp_m + i * 16 + arow) * ROW_B + (k0 + acol) * 2);
                ldsm4(af[i], sb + off);
            }
            #pragma unroll
            for (int jn = 0; jn < 4; jn++) {
                uint32_t off = (uint32_t)((warp_n + jn * 16 + brow) * ROW_B + (k0 + bcol) * 2);
                ldsm4(bf[jn], sb + MAT_BYTES + off);
            }
            #pragma unroll
            for (int i = 0; i < 4; i++) {
                #pragma unroll
                for (int n = 0; n < 8; n++) {
                    mma16816(acc[i][n], af[i],
                             bf[n >> 1][(n & 1) * 2], bf[n >> 1][(n & 1) * 2 + 1]);
                }
            }
        }
    }

    // epilogue: thread holds rows r0, r0+8; cols 2*(lane%4)
    #pragma unroll
    for (int i = 0; i < 4; i++) {
        int r0 = bm + warp_m + i * 16 + (lane >> 2);
        #pragma unroll
        for (int n = 0; n < 8; n++) {
            int col = bn + warp_n + n * 8 + (lane & 3) * 2;
            float2 u0 = make_float2(acc[i][n][0], acc[i][n][1]);
            float2 u1 = make_float2(acc[i][n][2], acc[i][n][3]);
            size_t o0 = (size_t)r0 * N + col;
            size_t o1 = (size_t)(r0 + 8) * N + col;
            if (Rp) {
                float2 q0 = *(const float2*)(Rp + o0);
                float2 q1 = *(const float2*)(Rp + o1);
                u0.x += q0.x; u0.y += q0.y; u1.x += q1.x; u1.y += q1.y;
            }
            *(float2*)(C + o0) = u0;
            *(float2*)(C + o1) = u1;
        }
    }
}

// ---------------- xp: [B,33] = x_main @ W_xp^T, 16 rows/block ----------------
// k-chunk 128; W_xp L2 traffic = 128 blocks * 540KB = 68 MB.
__global__ __launch_bounds__(256) void xp_kernel(const float* __restrict__ W_xp) {
    __shared__ float sx[16][128];
    __shared__ float sw[33][128];
    int tid = threadIdx.x, w = tid >> 5, lid = tid & 31;
    int b0 = blockIdx.x * 16;
    float acc[5][16];
    #pragma unroll
    for (int jj = 0; jj < 5; jj++)
        #pragma unroll
        for (int r = 0; r < 16; r++) acc[jj][r] = 0.0f;

    for (int kc = 0; kc < D_INNER; kc += 128) {
        {   // load 16 x 128 x_main block (512 float4)
            #pragma unroll
            for (int i = 0; i < 2; i++) {
                int idx = i * 256 + tid;           // < 512
                int r = idx >> 5, c = (idx & 31) << 2;
                *(float4*)&sx[r][c] =
                    *(const float4*)(g_xz + (size_t)(b0 + r) * (2 * D_INNER) + kc + c);
            }
        }
        {   // load 33 x 128 W_xp block (1056 float4)
            #pragma unroll
            for (int i = 0; i < 5; i++) {
                int idx = i * 256 + tid;
                if (idx < 33 * 32) {
                    int r = idx >> 5, c = (idx & 31) << 2;
                    *(float4*)&sw[r][c] = *(const float4*)(W_xp + (size_t)r * D_INNER + kc + c);
                }
            }
        }
        __syncthreads();
        #pragma unroll
        for (int jj = 0; jj < 5; jj++) {
            int j = w + jj * 8;
            if (j < 33) {
                #pragma unroll
                for (int kk = 0; kk < 4; kk++) {
                    float wv = sw[j][kk * 32 + lid];
                    #pragma unroll
                    for (int r = 0; r < 16; r++)
                        acc[jj][r] = fmaf(sx[r][kk * 32 + lid], wv, acc[jj][r]);
                }
            }
        }
        __syncthreads();
    }
    #pragma unroll
    for (int jj = 0; jj < 5; jj++) {
        int j = w + jj * 8;
        #pragma unroll
        for (int r = 0; r < 16; r++) {
            float a = acc[jj][r];
            #pragma unroll
            for (int o = 16; o; o >>= 1) a += __shfl_xor_sync(0xffffffffu, a, o);
            if (lid == 0 && j < 33) g_bcd[(size_t)(b0 + r) * 33 + j] = a;
        }
    }
}

// ---------------- elementwise SSM: 4 lanes per channel, coalesced h ---------
// Block: 256 threads = 64 channels of one batch row. Lane q in [0,4) handles
// h[d][4q..4q+3]; warp load = 512 contiguous bytes.
__global__ __launch_bounds__(256) void ssm2_kernel(const float* __restrict__ h,
                                                   const float* __restrict__ dt_bias,
                                                   const float* __restrict__ Dp,
                                                   float* __restrict__ h_new) {
    int blk = blockIdx.x;
    int b = blk >> 6;                              // row (64 chunks of 64 channels)
    int chunk = blk & 63;
    int tid = threadIdx.x;
    int d = chunk * 64 + (tid >> 2);               // channel
    int q = tid & 3;                               // quarter of D_STATE

    __shared__ float s_bc[33];
    if (tid < 33) s_bc[tid] = g_bcd[(size_t)b * 33 + tid];
    __syncthreads();

    float xm = g_xz[(size_t)b * (2 * D_INNER) + d];
    float t = s_bc[32] + dt_bias[d];
    float dlt = (t > 20.0f) ? t : log1pf(__expf(t));

    size_t off = ((size_t)b * D_INNER + d) * D_STATE + q * 4;
    float4 hv = __ldcs((const float4*)(h + off));
    float4 av = *(const float4*)(g_A + d * D_STATE + q * 4);
    float4 o;
    o.x = __expf(-dlt * av.x) * hv.x + dlt * s_bc[4*q + 0] * xm;
    o.y = __expf(-dlt * av.y) * hv.y + dlt * s_bc[4*q + 1] * xm;
    o.z = __expf(-dlt * av.z) * hv.z + dlt * s_bc[4*q + 2] * xm;
    o.w = __expf(-dlt * av.w) * hv.w + dlt * s_bc[4*q + 3] * xm;
    __stcs((float4*)(h_new + off), o);

    float acc = o.x * s_bc[16 + 4*q + 0] + o.y * s_bc[16 + 4*q + 1]
              + o.z * s_bc[16 + 4*q + 2] + o.w * s_bc[16 + 4*q + 3];
    acc += __shfl_xor_sync(0xffffffffu, acc, 1);
    acc += __shfl_xor_sync(0xffffffffu, acc, 2);

    if (q == 0) {
        float z = g_xz[(size_t)b * (2 * D_INNER) + D_INNER + d];
        float y = acc + Dp[d] * xm;
        float sig = 1.0f / (1.0f + __expf(-z));
        g_yg[(size_t)b * D_INNER + d] = __float2half(y * z * sig);
    }
}

// ---------------- launch ----------------
extern "C" void kernel_launch(void* const* d_in, const int* in_sizes, int n_in,
                              void* d_out, int out_size) {
    const float* x     = (const float*)d_in[0];
    const float* h     = (const float*)d_in[1];
    const float* W_in  = (const float*)d_in[2];
    const float* W_xp  = (const float*)d_in[3];
    const float* log_A = (const float*)d_in[4];
    const float* dt_b  = (const float*)d_in[5];
    const float* Dp    = (const float*)d_in[6];
    const float* W_out = (const float*)d_in[7];
    const float* gamma = (const float*)d_in[8];
    const float* beta  = (const float*)d_in[9];

    float* y_out = (float*)d_out;                         // [2048, 2048]
    float* h_out = y_out + (size_t)BATCH * D_MODEL;       // [2048, 4096, 16]

    void* p;
    cudaGetSymbolAddress(&p, g_xz);  float* xz = (float*)p;
    cudaGetSymbolAddress(&p, g_xh);  __half* xh = (__half*)p;
    cudaGetSymbolAddress(&p, g_wi);  __half* wi = (__half*)p;
    cudaGetSymbolAddress(&p, g_wo);  __half* wo = (__half*)p;
    cudaGetSymbolAddress(&p, g_yg);  __half* yg = (__half*)p;

    cudaFuncSetAttribute(gemm_mma_kernel, cudaFuncAttributeMaxDynamicSharedMemorySize, GEMM_SMEM);

    expA_kernel<<<(D_INNER * D_STATE + 255) / 256, 256>>>(log_A);

    int n4_wi = (2 * D_INNER * D_MODEL) / 4;
    cvt_kernel<<<(n4_wi + 255) / 256, 256>>>(W_in, wi, n4_wi);
    int n4_wo = (D_MODEL * D_INNER) / 4;
    cvt_kernel<<<(n4_wo + 255) / 256, 256>>>(W_out, wo, n4_wo);

    ln_kernel<<<BATCH, 256>>>(x, gamma, beta);

    // GEMM1: xz[B, 8192] = xn @ W_in^T
    gemm_mma_kernel<<<dim3(2 * D_INNER / 128, BATCH / 128), 128, GEMM_SMEM>>>(
        xh, wi, xz, nullptr, BATCH, 2 * D_INNER, D_MODEL);

    xp_kernel<<<BATCH / 16, 256>>>(W_xp);

    // SSM: 4 lanes per channel; grid = B * D_INNER * 4 / 256
    ssm2_kernel<<<BATCH * 64, 256>>>(h, dt_b, Dp, h_out);

    // GEMM2: y[B, 2048] = y_gated @ W_out^T + x
    gemm_mma_kernel<<<dim3(D_MODEL / 128, BATCH / 128), 128, GEMM_SMEM>>>(
        yg, wo, y_out, x, BATCH, D_MODEL, D_INNER);
}